// round 7
// baseline (speedup 1.0000x reference)
#include <cuda_runtime.h>
#include <math.h>

#define BATCH 128
#define NPTS  196
#define PDIM  768
#define DIM   384
#define KC    16
#define EE    8
#define NITERS 10
#define NCLS  1000
#define KSPLIT 8

// ---------------- scratch (device globals; no allocation allowed) ----------------
__device__ float g_xp[BATCH * NPTS * PDIM];
__device__ float g_patches[BATCH * NPTS * DIM];
__device__ float g_pn[BATCH * NPTS * DIM];
__device__ float g_clusters[BATCH * KC * DIM];
__device__ float g_c2[BATCH * KC * DIM];
__device__ float g_flat[BATCH * KC * DIM];
__device__ unsigned int g_mask[256];
__device__ float g_cpart[KSPLIT * BATCH * NCLS];

// ---------------- im2col: x[B,3,224,224] -> xp[B*196, 768] ----------------
__global__ void im2col_k(const float* __restrict__ x) {
    int idx = blockIdx.x * 256 + threadIdx.x;
    if (idx >= BATCH * NPTS * PDIM) return;
    int b   = idx / (NPTS * PDIM);
    int rem = idx - b * (NPTS * PDIM);
    int n   = rem / PDIM;
    int f   = rem - n * PDIM;
    int hp = n / 14, wp = n - hp * 14;
    int c  = f >> 8;
    int r2 = f & 255;
    int ph = r2 >> 4, pw_ = r2 & 15;
    g_xp[idx] = x[((b * 3 + c) * 224 + hp * 16 + ph) * 224 + wp * 16 + pw_];
}

// ---------------- patch GEMM: [25088,768] @ [768,384] + pb ----------------
__global__ __launch_bounds__(256) void gemm_patch(const float* __restrict__ Bw,
                                                  const float* __restrict__ bias) {
    __shared__ float As[16][132];
    __shared__ float Bs[16][68];
    int bm = blockIdx.y * 128, bn = blockIdx.x * 64;
    int tid = threadIdx.x;
    int ty = tid >> 4, tx = tid & 15;
    float acc[8][4];
#pragma unroll
    for (int i = 0; i < 8; i++)
#pragma unroll
        for (int j = 0; j < 4; j++) acc[i][j] = 0.f;

    for (int k0 = 0; k0 < PDIM; k0 += 16) {
#pragma unroll
        for (int l = 0; l < 2; l++) {
            int s = tid + l * 256;
            int row = s >> 2, kq = s & 3;
            float4 av = *(const float4*)&g_xp[(size_t)(bm + row) * PDIM + k0 + kq * 4];
            As[kq * 4 + 0][row] = av.x;
            As[kq * 4 + 1][row] = av.y;
            As[kq * 4 + 2][row] = av.z;
            As[kq * 4 + 3][row] = av.w;
        }
        {
            int row = tid >> 4, c4 = tid & 15;
            float4 bv = *(const float4*)&Bw[(k0 + row) * DIM + bn + c4 * 4];
            *(float4*)&Bs[row][c4 * 4] = bv;
        }
        __syncthreads();
#pragma unroll
        for (int kk = 0; kk < 16; kk++) {
            float4 a0 = *(const float4*)&As[kk][ty * 8];
            float4 a1 = *(const float4*)&As[kk][ty * 8 + 4];
            float4 bb = *(const float4*)&Bs[kk][tx * 4];
            float av[8] = {a0.x, a0.y, a0.z, a0.w, a1.x, a1.y, a1.z, a1.w};
            float bv[4] = {bb.x, bb.y, bb.z, bb.w};
#pragma unroll
            for (int i = 0; i < 8; i++)
#pragma unroll
                for (int j = 0; j < 4; j++) acc[i][j] += av[i] * bv[j];
        }
        __syncthreads();
    }
    int colg = bn + tx * 4;
    float4 b4 = *(const float4*)&bias[colg];
#pragma unroll
    for (int i = 0; i < 8; i++) {
        int rowg = bm + ty * 8 + i;
        float4 ov;
        ov.x = acc[i][0] + b4.x;
        ov.y = acc[i][1] + b4.y;
        ov.z = acc[i][2] + b4.z;
        ov.w = acc[i][3] + b4.w;
        *(float4*)&g_patches[(size_t)rowg * DIM + colg] = ov;
    }
}

// ---------------- LayerNorm per row (384), 128 threads/row ----------------
__global__ void ln_k(const float* __restrict__ gam, const float* __restrict__ bet) {
    int r = blockIdx.x, t = threadIdx.x;
    const float* row = g_patches + (size_t)r * DIM;
    float v0 = row[t], v1 = row[t + 128], v2 = row[t + 256];
    float s = v0 + v1 + v2;
    float s2 = v0 * v0 + v1 * v1 + v2 * v2;
#pragma unroll
    for (int o = 16; o > 0; o >>= 1) {
        s += __shfl_xor_sync(0xffffffffu, s, o);
        s2 += __shfl_xor_sync(0xffffffffu, s2, o);
    }
    __shared__ float aa[4], bb[4];
    if ((t & 31) == 0) { aa[t >> 5] = s; bb[t >> 5] = s2; }
    __syncthreads();
    float su = aa[0] + aa[1] + aa[2] + aa[3];
    float sq = bb[0] + bb[1] + bb[2] + bb[3];
    float mu = su * (1.f / 384.f);
    float var = sq * (1.f / 384.f) - mu * mu;
    float rstd = 1.f / sqrtf(var + 1e-5f);
    float* o = g_pn + (size_t)r * DIM;
    o[t]       = (v0 - mu) * rstd * gam[t]       + bet[t];
    o[t + 128] = (v1 - mu) * rstd * gam[t + 128] + bet[t + 128];
    o[t + 256] = (v2 - mu) * rstd * gam[t + 256] + bet[t + 256];
}

__global__ void clear_mask_k() { g_mask[threadIdx.x] = 0u; }

// ---------------- k-means: 10 iterations, one block per batch ----------------
__global__ __launch_bounds__(512) void kmeans_k(const float* __restrict__ pos) {
    extern __shared__ float sm[];
    float* centers = sm;             // KC*DIM
    float* accum   = sm + KC * DIM;  // KC*DIM
    __shared__ int   asgn[NPTS];
    __shared__ int   scnt[KC];
    __shared__ float csq[KC];
    int b = blockIdx.x, t = threadIdx.x;
    const float* pnb = g_pn + (size_t)b * NPTS * DIM;

    for (int e = t; e < KC * DIM; e += 512) {
        int k = e / DIM, d = e - k * DIM;
        centers[e] = pnb[(13 * k) * DIM + d];  // linspace(0,195,16) = 13*k
    }
    __syncthreads();

    for (int iter = 0; iter < NITERS; ++iter) {
        {   // ||c_k||^2: one warp per center
            int w = t >> 5, lane = t & 31;
            float p = 0.f;
#pragma unroll
            for (int i = 0; i < 12; i++) {
                float cv = centers[w * DIM + lane + 32 * i];
                p += cv * cv;
            }
#pragma unroll
            for (int o = 16; o > 0; o >>= 1) p += __shfl_xor_sync(0xffffffffu, p, o);
            if (lane == 0) csq[w] = p;
        }
        __syncthreads();
        {   // assignment: 2 threads per point (halves of d), combine via shfl
            int p = t >> 1; if (p > 195) p = 195;
            int h = t & 1;
            float acc[KC];
#pragma unroll
            for (int k = 0; k < KC; k++) acc[k] = 0.f;
            const float4* pn4 = (const float4*)pnb;
            const float4* c4  = (const float4*)centers;
            int pb4 = p * 96 + h * 48;
            int cb4 = h * 48;
            for (int i = 0; i < 48; i++) {
                float4 v = pn4[pb4 + i];
#pragma unroll
                for (int k = 0; k < KC; k++) {
                    float4 c = c4[k * 96 + cb4 + i];
                    acc[k] += v.x * c.x + v.y * c.y + v.z * c.z + v.w * c.w;
                }
            }
#pragma unroll
            for (int k = 0; k < KC; k++) acc[k] += __shfl_xor_sync(0xffffffffu, acc[k], 1);
            if ((t & 1) == 0 && (t >> 1) < NPTS) {
                float best = csq[0] - 2.f * acc[0];
                int bi = 0;
#pragma unroll
                for (int k = 1; k < KC; k++) {
                    float scv = csq[k] - 2.f * acc[k];
                    if (scv < best) { best = scv; bi = k; }
                }
                asgn[t >> 1] = bi;
            }
        }
        for (int e = t; e < KC * DIM; e += 512) accum[e] = 0.f;
        if (t < KC) scnt[t] = 0;
        __syncthreads();
        if (t < DIM) {  // each thread owns a d-column: conflict-free RMW
            for (int n = 0; n < NPTS; n++)
                accum[asgn[n] * DIM + t] += pnb[n * DIM + t];
        }
        if (t < NPTS) atomicAdd(&scnt[asgn[t]], 1);
        __syncthreads();
        float newc[KC];
        if (t < DIM) {
#pragma unroll
            for (int k = 0; k < KC; k++) {
                int c = scnt[k];
                newc[k] = (c > 0) ? (accum[k * DIM + t] / (float)c) : centers[k * DIM + t];
            }
        }
        __syncthreads();
        if (t < DIM) {
#pragma unroll
            for (int k = 0; k < KC; k++) centers[k * DIM + t] = newc[k];
        }
        __syncthreads();
    }
    for (int e = t; e < KC * DIM; e += 512)
        g_clusters[(size_t)b * KC * DIM + e] = centers[e] + pos[e];
}

// 16xD @ DxD (+bias, optional exact GELU); In in smem, thread t = output col
__device__ __forceinline__ void mm16(const float* __restrict__ In,
                                     const float* __restrict__ W,
                                     const float* __restrict__ bias,
                                     float* __restrict__ Out, int t, int gelu) {
    float acc[KC];
#pragma unroll
    for (int k = 0; k < KC; k++) acc[k] = 0.f;
    const float4* I4 = (const float4*)In;
    for (int i = 0; i < 96; i++) {
        int d0 = i * 4;
        float w0 = W[(d0 + 0) * DIM + t];
        float w1 = W[(d0 + 1) * DIM + t];
        float w2 = W[(d0 + 2) * DIM + t];
        float w3 = W[(d0 + 3) * DIM + t];
#pragma unroll
        for (int k = 0; k < KC; k++) {
            float4 a = I4[k * 96 + i];
            acc[k] += a.x * w0 + a.y * w1 + a.z * w2 + a.w * w3;
        }
    }
    float bv = bias[t];
#pragma unroll
    for (int k = 0; k < KC; k++) {
        float v = acc[k] + bv;
        if (gelu) v = 0.5f * v * (1.f + erff(v * 0.70710678118654752f));
        Out[k * DIM + t] = v;
    }
}

// ---------------- attention + hypergraph + MLP + sim-mask (block = batch) ----------
__global__ __launch_bounds__(384) void attn_k(
    const float* __restrict__ qw, const float* __restrict__ qb,
    const float* __restrict__ kw, const float* __restrict__ kb,
    const float* __restrict__ vw, const float* __restrict__ vb,
    const float* __restrict__ ew, const float* __restrict__ eb,
    const float* __restrict__ nw, const float* __restrict__ nb,
    const float* __restrict__ m1w, const float* __restrict__ m1b,
    const float* __restrict__ m2w, const float* __restrict__ m2b) {
    extern __shared__ float sm[];
    float* A  = sm;
    float* Bq = sm + 6144;
    float* Ck = sm + 12288;
    float* Dv = sm + 18432;
    __shared__ float sc[KC * KC];
    __shared__ float hsc[KC * EE];
    __shared__ float rDd[EE];
    __shared__ float Lm[EE * EE];
    __shared__ float nrm[KC];
    __shared__ float pna[256];
    int b = blockIdx.x, t = threadIdx.x;  // t = d (384 threads)

#pragma unroll
    for (int k = 0; k < KC; k++) A[k * DIM + t] = g_clusters[(size_t)b * KC * DIM + k * DIM + t];
    __syncthreads();

    {   // fused Q,K,V
        float aq[KC], ak[KC], av[KC];
#pragma unroll
        for (int k = 0; k < KC; k++) { aq[k] = 0.f; ak[k] = 0.f; av[k] = 0.f; }
        const float4* A4 = (const float4*)A;
        for (int i = 0; i < 96; i++) {
            int d0 = i * 4;
            float q0 = qw[(d0 + 0) * DIM + t], q1 = qw[(d0 + 1) * DIM + t];
            float q2 = qw[(d0 + 2) * DIM + t], q3 = qw[(d0 + 3) * DIM + t];
            float k0 = kw[(d0 + 0) * DIM + t], k1 = kw[(d0 + 1) * DIM + t];
            float k2 = kw[(d0 + 2) * DIM + t], k3 = kw[(d0 + 3) * DIM + t];
            float v0 = vw[(d0 + 0) * DIM + t], v1 = vw[(d0 + 1) * DIM + t];
            float v2 = vw[(d0 + 2) * DIM + t], v3 = vw[(d0 + 3) * DIM + t];
#pragma unroll
            for (int k = 0; k < KC; k++) {
                float4 a = A4[k * 96 + i];
                aq[k] += a.x * q0 + a.y * q1 + a.z * q2 + a.w * q3;
                ak[k] += a.x * k0 + a.y * k1 + a.z * k2 + a.w * k3;
                av[k] += a.x * v0 + a.y * v1 + a.z * v2 + a.w * v3;
            }
        }
        float qbv = qb[t], kbv = kb[t], vbv = vb[t];
#pragma unroll
        for (int k = 0; k < KC; k++) {
            Bq[k * DIM + t] = aq[k] + qbv;
            Ck[k * DIM + t] = ak[k] + kbv;
            Dv[k * DIM + t] = av[k] + vbv;
        }
    }
    __syncthreads();
    if (t < 256) {  // scores
        int q = t >> 4, kk = t & 15;
        const float4* Q4 = (const float4*)Bq;
        const float4* K4 = (const float4*)Ck;
        float s = 0.f;
        for (int i = 0; i < 96; i++) {
            float4 a = Q4[q * 96 + i];
            float4 c = K4[kk * 96 + i];
            s += a.x * c.x + a.y * c.y + a.z * c.z + a.w * c.w;
        }
        sc[t] = s * 0.05103103630798288f;  // 1/sqrt(384)
    }
    __syncthreads();
    if (t < KC) {  // softmax over k
        float m = -1e30f;
#pragma unroll
        for (int k = 0; k < KC; k++) m = fmaxf(m, sc[t * 16 + k]);
        float e[KC], su = 0.f;
#pragma unroll
        for (int k = 0; k < KC; k++) { e[k] = expf(sc[t * 16 + k] - m); su += e[k]; }
        float inv = 1.f / su;
#pragma unroll
        for (int k = 0; k < KC; k++) sc[t * 16 + k] = e[k] * inv;
    }
    __syncthreads();
    {   // attn @ V -> A
        float nv[KC];
#pragma unroll
        for (int q = 0; q < KC; q++) {
            float s = 0.f;
#pragma unroll
            for (int k = 0; k < KC; k++) s += sc[q * 16 + k] * Dv[k * DIM + t];
            nv[q] = s;
        }
#pragma unroll
        for (int q = 0; q < KC; q++) A[q * DIM + t] = nv[q];
    }
    __syncthreads();
    if (t < 128) {  // hyperedge logits
        int k = t >> 3, e = t & 7;
        float s = 0.f;
        for (int d = 0; d < DIM; d++) s += A[k * DIM + d] * ew[d * EE + e];
        hsc[k * EE + e] = s + eb[e];
    }
    __syncthreads();
    if (t < EE) {  // softmax over clusters; degree
        float m = -1e30f;
#pragma unroll
        for (int k = 0; k < KC; k++) m = fmaxf(m, hsc[k * EE + t]);
        float ex[KC], su = 0.f;
#pragma unroll
        for (int k = 0; k < KC; k++) { ex[k] = expf(hsc[k * EE + t] - m); su += ex[k]; }
        float inv = 1.f / su, dd = 0.f;
#pragma unroll
        for (int k = 0; k < KC; k++) { float h = ex[k] * inv; hsc[k * EE + t] = h; dd += h; }
        rDd[t] = 1.f / sqrtf(dd);
    }
    __syncthreads();
    if (t < 64) {  // L = I - D^-1/2 H H^T   (row-scaled, like reference)
        int e = t >> 3, f = t & 7;
        float s = 0.f;
#pragma unroll
        for (int k = 0; k < KC; k++) s += hsc[k * EE + e] * hsc[k * EE + f];
        Lm[t] = ((e == f) ? 1.f : 0.f) - rDd[e] * s;
    }
    __syncthreads();
    {   // padded L @ clusters -> Bq (rows >= E zero)
        float lv[EE];
#pragma unroll
        for (int i = 0; i < EE; i++) {
            float s = 0.f;
#pragma unroll
            for (int f = 0; f < EE; f++) s += Lm[i * EE + f] * A[f * DIM + t];
            lv[i] = s;
        }
#pragma unroll
        for (int i = 0; i < EE; i++) Bq[i * DIM + t] = lv[i];
#pragma unroll
        for (int i = EE; i < KC; i++) Bq[i * DIM + t] = 0.f;
    }
    __syncthreads();
    mm16(Bq, nw, nb, Ck, t, 0);
    __syncthreads();
    mm16(Ck, m1w, m1b, Dv, t, 1);
    __syncthreads();
    mm16(Dv, m2w, m2b, A, t, 0);
    __syncthreads();
#pragma unroll
    for (int k = 0; k < KC; k++) g_c2[(size_t)b * KC * DIM + k * DIM + t] = A[k * DIM + t];
    if (t < 256) {  // partial norms
        int k = t >> 4, l = t & 15;
        float s = 0.f;
#pragma unroll
        for (int i = 0; i < 24; i++) {
            float v = A[k * DIM + l + 16 * i];
            s += v * v;
        }
        pna[t] = s;
    }
    __syncthreads();
    if (t < KC) {
        float s = 0.f;
#pragma unroll
        for (int l = 0; l < 16; l++) s += pna[t * 16 + l];
        nrm[t] = fmaxf(sqrtf(s), 1e-12f);
    }
    __syncthreads();
    if (t < 120) {  // cosine-sim mask, OR over batch
        int i = 0, rem = t, cnt = 15;
        while (rem >= cnt) { rem -= cnt; cnt--; i++; }
        int j = i + 1 + rem;
        float s = 0.f;
        for (int d = 0; d < DIM; d++) s += A[i * DIM + d] * A[j * DIM + d];
        if (s / (nrm[i] * nrm[j]) > 0.9f) atomicOr(&g_mask[i * 16 + j], 1u);
    }
}

// ---------------- sequential merge + gated fusion (block = batch) ----------------
__global__ __launch_bounds__(384) void merge_k(const float* __restrict__ fbw,
                                               const float* __restrict__ fbb,
                                               const float* __restrict__ fgw,
                                               const float* __restrict__ fgb) {
    __shared__ unsigned int msk[256];
    __shared__ float gsh[DIM];
    __shared__ float wsum[12];
    __shared__ float gate_s;
    int b = blockIdx.x, t = threadIdx.x;
    if (t < 256) msk[t] = g_mask[t];
    float c[KC];
#pragma unroll
    for (int k = 0; k < KC; k++) c[k] = g_c2[(size_t)b * KC * DIM + k * DIM + t];
    __syncthreads();
#pragma unroll
    for (int i = 0; i < KC; i++)
#pragma unroll
        for (int j = i + 1; j < KC; j++)
            if (msk[i * 16 + j]) {
                float m = (c[i] + c[j]) * 0.5f;
                c[i] = m;
                c[j] = m;
            }
    float g = 0.f;
#pragma unroll
    for (int k = 0; k < KC; k++) g += c[k];
    g *= (1.f / 16.f);
    gsh[t] = g;
    float p = g * fgw[t];
#pragma unroll
    for (int o = 16; o > 0; o >>= 1) p += __shfl_xor_sync(0xffffffffu, p, o);
    if ((t & 31) == 0) wsum[t >> 5] = p;
    __syncthreads();
    if (t == 0) {
        float s = 0.f;
#pragma unroll
        for (int i = 0; i < 12; i++) s += wsum[i];
        gate_s = 1.f / (1.f + expf(-(s + fgb[0])));
    }
    __syncthreads();
    float gate = gate_s;
    float acc = 0.f;
    for (int d = 0; d < DIM; d++) acc += gsh[d] * fbw[d * DIM + t];
    float fb = acc + fbb[t];
#pragma unroll
    for (int k = 0; k < KC; k++)
        g_flat[(size_t)b * KC * DIM + k * DIM + t] = c[k] + fb * gate;
}

// ---------------- classifier: [128,6144] @ [6144,1000], split-K ----------------
__global__ __launch_bounds__(256) void cls_k(const float* __restrict__ cw) {
    __shared__ float As[16][132];
    __shared__ float Bs[16][68];
    int bn = blockIdx.x * 64;
    int kz = blockIdx.z;
    int kbase = kz * (KC * DIM / KSPLIT);  // 768 per split
    int tid = threadIdx.x;
    int ty = tid >> 4, tx = tid & 15;
    float acc[8][4];
#pragma unroll
    for (int i = 0; i < 8; i++)
#pragma unroll
        for (int j = 0; j < 4; j++) acc[i][j] = 0.f;

    for (int k0 = kbase; k0 < kbase + 768; k0 += 16) {
#pragma unroll
        for (int l = 0; l < 2; l++) {
            int s = tid + l * 256;
            int row = s >> 2, kq = s & 3;
            float4 av = *(const float4*)&g_flat[(size_t)row * (KC * DIM) + k0 + kq * 4];
            As[kq * 4 + 0][row] = av.x;
            As[kq * 4 + 1][row] = av.y;
            As[kq * 4 + 2][row] = av.z;
            As[kq * 4 + 3][row] = av.w;
        }
#pragma unroll
        for (int j = 0; j < 4; j++) {
            int idx = tid * 4 + j;
            int row = idx >> 6, cc = idx & 63;
            int n = bn + cc;
            Bs[row][cc] = (n < NCLS) ? cw[(size_t)(k0 + row) * NCLS + n] : 0.f;
        }
        __syncthreads();
#pragma unroll
        for (int kk = 0; kk < 16; kk++) {
            float4 a0 = *(const float4*)&As[kk][ty * 8];
            float4 a1 = *(const float4*)&As[kk][ty * 8 + 4];
            float4 bb = *(const float4*)&Bs[kk][tx * 4];
            float av[8] = {a0.x, a0.y, a0.z, a0.w, a1.x, a1.y, a1.z, a1.w};
            float bv[4] = {bb.x, bb.y, bb.z, bb.w};
#pragma unroll
            for (int i = 0; i < 8; i++)
#pragma unroll
                for (int j = 0; j < 4; j++) acc[i][j] += av[i] * bv[j];
        }
        __syncthreads();
    }
    float* part = g_cpart + (size_t)kz * BATCH * NCLS;
#pragma unroll
    for (int i = 0; i < 8; i++)
#pragma unroll
        for (int j = 0; j < 4; j++) {
            int n = bn + tx * 4 + j;
            if (n < NCLS) part[(ty * 8 + i) * NCLS + n] = acc[i][j];
        }
}

__global__ void finout_k(const float* __restrict__ cb, float* __restrict__ out) {
    int idx = blockIdx.x * 256 + threadIdx.x;
    if (idx >= BATCH * NCLS) return;
    int n = idx % NCLS;
    float s = cb[n];
#pragma unroll
    for (int z = 0; z < KSPLIT; z++) s += g_cpart[(size_t)z * BATCH * NCLS + idx];
    out[idx] = s;
}

extern "C" void kernel_launch(void* const* d_in, const int* in_sizes, int n_in,
                              void* d_out, int out_size) {
    const float* x    = (const float*)d_in[0];
    const float* pw   = (const float*)d_in[1];
    const float* pb   = (const float*)d_in[2];
    const float* ln_g = (const float*)d_in[3];
    const float* ln_b = (const float*)d_in[4];
    const float* pos  = (const float*)d_in[5];
    const float* qw   = (const float*)d_in[6];
    const float* qb   = (const float*)d_in[7];
    const float* kw   = (const float*)d_in[8];
    const float* kb   = (const float*)d_in[9];
    const float* vw   = (const float*)d_in[10];
    const float* vb   = (const float*)d_in[11];
    const float* ew   = (const float*)d_in[12];
    const float* eb   = (const float*)d_in[13];
    const float* nw   = (const float*)d_in[14];
    const float* nb   = (const float*)d_in[15];
    const float* m1w  = (const float*)d_in[16];
    const float* m1b  = (const float*)d_in[17];
    const float* m2w  = (const float*)d_in[18];
    const float* m2b  = (const float*)d_in[19];
    const float* fbw  = (const float*)d_in[20];
    const float* fbb  = (const float*)d_in[21];
    const float* fgw  = (const float*)d_in[22];
    const float* fgb  = (const float*)d_in[23];
    const float* cw   = (const float*)d_in[24];
    const float* cb   = (const float*)d_in[25];
    float* out = (float*)d_out;

    cudaFuncSetAttribute(kmeans_k, cudaFuncAttributeMaxDynamicSharedMemorySize, 49152);
    cudaFuncSetAttribute(attn_k,   cudaFuncAttributeMaxDynamicSharedMemorySize, 98304);

    int tot = BATCH * NPTS * PDIM;
    im2col_k<<<(tot + 255) / 256, 256>>>(x);
    gemm_patch<<<dim3(6, 196), 256>>>(pw, pb);
    ln_k<<<BATCH * NPTS, 128>>>(ln_g, ln_b);
    clear_mask_k<<<1, 256>>>();
    kmeans_k<<<BATCH, 512, 49152>>>(pos);
    attn_k<<<BATCH, 384, 98304>>>(qw, qb, kw, kb, vw, vb, ew, eb, nw, nb,
                                  m1w, m1b, m2w, m2b);
    merge_k<<<BATCH, 384>>>(fbw, fbb, fgw, fgb);
    cls_k<<<dim3(16, 1, KSPLIT), 256>>>(cw);
    finout_k<<<(BATCH * NCLS + 255) / 256, 256>>>(cb, out);
}

// round 8
// speedup vs baseline: 1.1262x; 1.1262x over previous
#include <cuda_runtime.h>
#include <math.h>

#define BATCH 128
#define NPTS  196
#define PDIM  768
#define DIM   384
#define KC    16
#define EE    8
#define NITERS 10
#define NCLS  1000
#define KSPLIT 8

// ---------------- scratch (device globals; no allocation allowed) ----------------
__device__ float g_patches[BATCH * NPTS * DIM];
__device__ float g_pn[BATCH * NPTS * DIM];
__device__ float g_clusters[BATCH * KC * DIM];
__device__ float g_c2[BATCH * KC * DIM];
__device__ float g_flat[BATCH * KC * DIM];
__device__ unsigned int g_mask[256];
__device__ float g_cpart[KSPLIT * BATCH * NCLS];

// ---------------- patch GEMM with fused im2col: [25088,768] @ [768,384] + pb ------
// BM=128, BN=128, BK=16, 256 threads, 8x8 microtile (split +-64), reg double buffer
__global__ __launch_bounds__(256) void gemm_patch(const float* __restrict__ x,
                                                  const float* __restrict__ Bw,
                                                  const float* __restrict__ bias) {
    __shared__ float As[16][132];
    __shared__ float Bs[16][132];
    int bm = blockIdx.y * 128, bn = blockIdx.x * 128;
    int tid = threadIdx.x;
    int ty = tid >> 4, tx = tid & 15;

    // A loader: slot l covers row tid>>2 (+64*l), k-quad kq = tid&3
    int kqA = tid & 3;
    int rowA[2];
    size_t baseA[2];
#pragma unroll
    for (int l = 0; l < 2; l++) {
        rowA[l] = (tid >> 2) + l * 64;
        int r = bm + rowA[l];
        int b = r / 196;
        int n = r - b * 196;
        int hp = n / 14, wp = n - hp * 14;
        baseA[l] = ((size_t)(b * 3) * 224 + hp * 16) * 224 + wp * 16;
    }
    // B loader: slot l covers k-row tid>>5 + l*8, col quad (tid&31)*4
    int rB0 = tid >> 5;
    int cB = (tid & 31) * 4;

    float4 aReg[2], bReg[2];
#pragma unroll
    for (int l = 0; l < 2; l++) {
        int k = 0 + kqA * 4;
        int c = k >> 8, ph = (k >> 4) & 15, pw = k & 15;
        aReg[l] = *(const float4*)&x[baseA[l] + (size_t)c * 50176 + ph * 224 + pw];
        bReg[l] = *(const float4*)&Bw[(size_t)(rB0 + l * 8) * DIM + bn + cB];
    }

    float acc[8][8];
#pragma unroll
    for (int i = 0; i < 8; i++)
#pragma unroll
        for (int j = 0; j < 8; j++) acc[i][j] = 0.f;

    for (int k0 = 0; k0 < PDIM; k0 += 16) {
#pragma unroll
        for (int l = 0; l < 2; l++) {
            As[kqA * 4 + 0][rowA[l]] = aReg[l].x;
            As[kqA * 4 + 1][rowA[l]] = aReg[l].y;
            As[kqA * 4 + 2][rowA[l]] = aReg[l].z;
            As[kqA * 4 + 3][rowA[l]] = aReg[l].w;
            *(float4*)&Bs[rB0 + l * 8][cB] = bReg[l];
        }
        __syncthreads();
        if (k0 + 16 < PDIM) {
            int kn = k0 + 16;
#pragma unroll
            for (int l = 0; l < 2; l++) {
                int k = kn + kqA * 4;
                int c = k >> 8, ph = (k >> 4) & 15, pw = k & 15;
                aReg[l] = *(const float4*)&x[baseA[l] + (size_t)c * 50176 + ph * 224 + pw];
                bReg[l] = *(const float4*)&Bw[(size_t)(kn + rB0 + l * 8) * DIM + bn + cB];
            }
        }
#pragma unroll
        for (int kk = 0; kk < 16; kk++) {
            float4 a0 = *(const float4*)&As[kk][ty * 4];
            float4 a1 = *(const float4*)&As[kk][64 + ty * 4];
            float4 b0 = *(const float4*)&Bs[kk][tx * 4];
            float4 b1 = *(const float4*)&Bs[kk][64 + tx * 4];
            float av[8] = {a0.x, a0.y, a0.z, a0.w, a1.x, a1.y, a1.z, a1.w};
            float bv[8] = {b0.x, b0.y, b0.z, b0.w, b1.x, b1.y, b1.z, b1.w};
#pragma unroll
            for (int i = 0; i < 8; i++)
#pragma unroll
                for (int j = 0; j < 8; j++) acc[i][j] += av[i] * bv[j];
        }
        __syncthreads();
    }

    int col0 = bn + tx * 4, col1 = bn + 64 + tx * 4;
    float4 bi0 = *(const float4*)&bias[col0];
    float4 bi1 = *(const float4*)&bias[col1];
#pragma unroll
    for (int i = 0; i < 8; i++) {
        int rowg = bm + ((i < 4) ? (ty * 4 + i) : (64 + ty * 4 + i - 4));
        float4 o0, o1;
        o0.x = acc[i][0] + bi0.x; o0.y = acc[i][1] + bi0.y;
        o0.z = acc[i][2] + bi0.z; o0.w = acc[i][3] + bi0.w;
        o1.x = acc[i][4] + bi1.x; o1.y = acc[i][5] + bi1.y;
        o1.z = acc[i][6] + bi1.z; o1.w = acc[i][7] + bi1.w;
        *(float4*)&g_patches[(size_t)rowg * DIM + col0] = o0;
        *(float4*)&g_patches[(size_t)rowg * DIM + col1] = o1;
    }
}

// ---------------- LayerNorm per row (384), 128 threads/row ----------------
__global__ void ln_k(const float* __restrict__ gam, const float* __restrict__ bet) {
    int r = blockIdx.x, t = threadIdx.x;
    const float* row = g_patches + (size_t)r * DIM;
    float v0 = row[t], v1 = row[t + 128], v2 = row[t + 256];
    float s = v0 + v1 + v2;
    float s2 = v0 * v0 + v1 * v1 + v2 * v2;
#pragma unroll
    for (int o = 16; o > 0; o >>= 1) {
        s += __shfl_xor_sync(0xffffffffu, s, o);
        s2 += __shfl_xor_sync(0xffffffffu, s2, o);
    }
    __shared__ float aa[4], bb[4];
    if ((t & 31) == 0) { aa[t >> 5] = s; bb[t >> 5] = s2; }
    __syncthreads();
    float su = aa[0] + aa[1] + aa[2] + aa[3];
    float sq = bb[0] + bb[1] + bb[2] + bb[3];
    float mu = su * (1.f / 384.f);
    float var = sq * (1.f / 384.f) - mu * mu;
    float rstd = 1.f / sqrtf(var + 1e-5f);
    float* o = g_pn + (size_t)r * DIM;
    o[t]       = (v0 - mu) * rstd * gam[t]       + bet[t];
    o[t + 128] = (v1 - mu) * rstd * gam[t + 128] + bet[t + 128];
    o[t + 256] = (v2 - mu) * rstd * gam[t + 256] + bet[t + 256];
}

// ---------------- k-means: 10 iterations, one block per batch ----------------
// assignment: 4 points per thread, quarter-D per thread (49 groups x 4 quarters)
__global__ __launch_bounds__(512) void kmeans_k(const float* __restrict__ pos) {
    extern __shared__ float sm[];
    float* centers = sm;             // KC*DIM
    float* accum   = sm + KC * DIM;  // KC*DIM
    __shared__ int   asgn[NPTS];
    __shared__ int   scnt[KC];
    __shared__ float csq[KC];
    int b = blockIdx.x, t = threadIdx.x;
    const float* pnb = g_pn + (size_t)b * NPTS * DIM;

    if (b == 0 && t < 256) g_mask[t] = 0u;  // clear merge mask (pre-attn)

    for (int e = t; e < KC * DIM; e += 512) {
        int k = e / DIM, d = e - k * DIM;
        centers[e] = pnb[(13 * k) * DIM + d];  // linspace(0,195,16) = 13*k
    }
    __syncthreads();

    for (int iter = 0; iter < NITERS; ++iter) {
        {   // ||c_k||^2: one warp per center
            int w = t >> 5, lane = t & 31;
            float p = 0.f;
#pragma unroll
            for (int i = 0; i < 12; i++) {
                float cv = centers[w * DIM + lane + 32 * i];
                p += cv * cv;
            }
#pragma unroll
            for (int o = 16; o > 0; o >>= 1) p += __shfl_xor_sync(0xffffffffu, p, o);
            if (lane == 0) csq[w] = p;
        }
        __syncthreads();
        if (t < 224) {  // assignment (warps 0-6 fully active for shfl)
            int tt = (t < 196) ? t : 195;
            int g = tt >> 2, q = tt & 3;
            int p0 = 4 * g;
            int fb = q * 24;  // quarter of the 96 float4s
            float acc[4][KC];
#pragma unroll
            for (int p = 0; p < 4; p++)
#pragma unroll
                for (int k = 0; k < KC; k++) acc[p][k] = 0.f;
            const float4* pn4 = (const float4*)pnb;
            const float4* c4  = (const float4*)centers;
            for (int i = 0; i < 24; i++) {
                float4 v0 = pn4[(p0 + 0) * 96 + fb + i];
                float4 v1 = pn4[(p0 + 1) * 96 + fb + i];
                float4 v2 = pn4[(p0 + 2) * 96 + fb + i];
                float4 v3 = pn4[(p0 + 3) * 96 + fb + i];
#pragma unroll
                for (int k = 0; k < KC; k++) {
                    float4 c = c4[k * 96 + fb + i];
                    acc[0][k] += v0.x * c.x + v0.y * c.y + v0.z * c.z + v0.w * c.w;
                    acc[1][k] += v1.x * c.x + v1.y * c.y + v1.z * c.z + v1.w * c.w;
                    acc[2][k] += v2.x * c.x + v2.y * c.y + v2.z * c.z + v2.w * c.w;
                    acc[3][k] += v3.x * c.x + v3.y * c.y + v3.z * c.z + v3.w * c.w;
                }
            }
            // combine the 4 quarters (threads 4g..4g+3 are lane-adjacent)
#pragma unroll
            for (int p = 0; p < 4; p++)
#pragma unroll
                for (int k = 0; k < KC; k++) {
                    float r = acc[p][k];
                    r += __shfl_xor_sync(0xffffffffu, r, 1);
                    r += __shfl_xor_sync(0xffffffffu, r, 2);
                    acc[p][k] = r;
                }
            if (q == 0 && t < 196) {
#pragma unroll
                for (int p = 0; p < 4; p++) {
                    float best = csq[0] - 2.f * acc[p][0];
                    int bi = 0;
#pragma unroll
                    for (int k = 1; k < KC; k++) {
                        float scv = csq[k] - 2.f * acc[p][k];
                        if (scv < best) { best = scv; bi = k; }
                    }
                    asgn[p0 + p] = bi;
                }
            }
        }
        for (int e = t; e < KC * DIM; e += 512) accum[e] = 0.f;
        if (t < KC) scnt[t] = 0;
        __syncthreads();
        if (t < DIM) {  // each thread owns a d-column: conflict-free RMW
            for (int n = 0; n < NPTS; n++)
                accum[asgn[n] * DIM + t] += pnb[n * DIM + t];
        }
        if (t < NPTS) atomicAdd(&scnt[asgn[t]], 1);
        __syncthreads();
        float newc[KC];
        if (t < DIM) {
#pragma unroll
            for (int k = 0; k < KC; k++) {
                int c = scnt[k];
                newc[k] = (c > 0) ? (accum[k * DIM + t] / (float)c) : centers[k * DIM + t];
            }
        }
        __syncthreads();
        if (t < DIM) {
#pragma unroll
            for (int k = 0; k < KC; k++) centers[k * DIM + t] = newc[k];
        }
        __syncthreads();
    }
    for (int e = t; e < KC * DIM; e += 512)
        g_clusters[(size_t)b * KC * DIM + e] = centers[e] + pos[e];
}

// 16xD @ DxD (+bias, optional exact GELU); In in smem, thread t = output col
__device__ __forceinline__ void mm16(const float* __restrict__ In,
                                     const float* __restrict__ W,
                                     const float* __restrict__ bias,
                                     float* __restrict__ Out, int t, int gelu) {
    float acc[KC];
#pragma unroll
    for (int k = 0; k < KC; k++) acc[k] = 0.f;
    const float4* I4 = (const float4*)In;
    for (int i = 0; i < 96; i++) {
        int d0 = i * 4;
        float w0 = W[(d0 + 0) * DIM + t];
        float w1 = W[(d0 + 1) * DIM + t];
        float w2 = W[(d0 + 2) * DIM + t];
        float w3 = W[(d0 + 3) * DIM + t];
#pragma unroll
        for (int k = 0; k < KC; k++) {
            float4 a = I4[k * 96 + i];
            acc[k] += a.x * w0 + a.y * w1 + a.z * w2 + a.w * w3;
        }
    }
    float bv = bias[t];
#pragma unroll
    for (int k = 0; k < KC; k++) {
        float v = acc[k] + bv;
        if (gelu) v = 0.5f * v * (1.f + erff(v * 0.70710678118654752f));
        Out[k * DIM + t] = v;
    }
}

// ---------------- attention + hypergraph + MLP + sim-mask (block = batch) ----------
__global__ __launch_bounds__(384) void attn_k(
    const float* __restrict__ qw, const float* __restrict__ qb,
    const float* __restrict__ kw, const float* __restrict__ kb,
    const float* __restrict__ vw, const float* __restrict__ vb,
    const float* __restrict__ ew, const float* __restrict__ eb,
    const float* __restrict__ nw, const float* __restrict__ nb,
    const float* __restrict__ m1w, const float* __restrict__ m1b,
    const float* __restrict__ m2w, const float* __restrict__ m2b) {
    extern __shared__ float sm[];
    float* A  = sm;
    float* Bq = sm + 6144;
    float* Ck = sm + 12288;
    float* Dv = sm + 18432;
    __shared__ float sc[KC * KC];
    __shared__ float hsc[KC * EE];
    __shared__ float rDd[EE];
    __shared__ float Lm[EE * EE];
    __shared__ float nrm[KC];
    __shared__ float pna[256];
    int b = blockIdx.x, t = threadIdx.x;  // t = d (384 threads)

#pragma unroll
    for (int k = 0; k < KC; k++) A[k * DIM + t] = g_clusters[(size_t)b * KC * DIM + k * DIM + t];
    __syncthreads();

    {   // fused Q,K,V
        float aq[KC], ak[KC], av[KC];
#pragma unroll
        for (int k = 0; k < KC; k++) { aq[k] = 0.f; ak[k] = 0.f; av[k] = 0.f; }
        const float4* A4 = (const float4*)A;
        for (int i = 0; i < 96; i++) {
            int d0 = i * 4;
            float q0 = qw[(d0 + 0) * DIM + t], q1 = qw[(d0 + 1) * DIM + t];
            float q2 = qw[(d0 + 2) * DIM + t], q3 = qw[(d0 + 3) * DIM + t];
            float k0 = kw[(d0 + 0) * DIM + t], k1 = kw[(d0 + 1) * DIM + t];
            float k2 = kw[(d0 + 2) * DIM + t], k3 = kw[(d0 + 3) * DIM + t];
            float v0 = vw[(d0 + 0) * DIM + t], v1 = vw[(d0 + 1) * DIM + t];
            float v2 = vw[(d0 + 2) * DIM + t], v3 = vw[(d0 + 3) * DIM + t];
#pragma unroll
            for (int k = 0; k < KC; k++) {
                float4 a = A4[k * 96 + i];
                aq[k] += a.x * q0 + a.y * q1 + a.z * q2 + a.w * q3;
                ak[k] += a.x * k0 + a.y * k1 + a.z * k2 + a.w * k3;
                av[k] += a.x * v0 + a.y * v1 + a.z * v2 + a.w * v3;
            }
        }
        float qbv = qb[t], kbv = kb[t], vbv = vb[t];
#pragma unroll
        for (int k = 0; k < KC; k++) {
            Bq[k * DIM + t] = aq[k] + qbv;
            Ck[k * DIM + t] = ak[k] + kbv;
            Dv[k * DIM + t] = av[k] + vbv;
        }
    }
    __syncthreads();
    if (t < 256) {  // scores
        int q = t >> 4, kk = t & 15;
        const float4* Q4 = (const float4*)Bq;
        const float4* K4 = (const float4*)Ck;
        float s = 0.f;
        for (int i = 0; i < 96; i++) {
            float4 a = Q4[q * 96 + i];
            float4 c = K4[kk * 96 + i];
            s += a.x * c.x + a.y * c.y + a.z * c.z + a.w * c.w;
        }
        sc[t] = s * 0.05103103630798288f;  // 1/sqrt(384)
    }
    __syncthreads();
    if (t < KC) {  // softmax over k
        float m = -1e30f;
#pragma unroll
        for (int k = 0; k < KC; k++) m = fmaxf(m, sc[t * 16 + k]);
        float e[KC], su = 0.f;
#pragma unroll
        for (int k = 0; k < KC; k++) { e[k] = expf(sc[t * 16 + k] - m); su += e[k]; }
        float inv = 1.f / su;
#pragma unroll
        for (int k = 0; k < KC; k++) sc[t * 16 + k] = e[k] * inv;
    }
    __syncthreads();
    {   // attn @ V -> A
        float nv[KC];
#pragma unroll
        for (int q = 0; q < KC; q++) {
            float s = 0.f;
#pragma unroll
            for (int k = 0; k < KC; k++) s += sc[q * 16 + k] * Dv[k * DIM + t];
            nv[q] = s;
        }
#pragma unroll
        for (int q = 0; q < KC; q++) A[q * DIM + t] = nv[q];
    }
    __syncthreads();
    if (t < 128) {  // hyperedge logits
        int k = t >> 3, e = t & 7;
        float s = 0.f;
        for (int d = 0; d < DIM; d++) s += A[k * DIM + d] * ew[d * EE + e];
        hsc[k * EE + e] = s + eb[e];
    }
    __syncthreads();
    if (t < EE) {  // softmax over clusters; degree
        float m = -1e30f;
#pragma unroll
        for (int k = 0; k < KC; k++) m = fmaxf(m, hsc[k * EE + t]);
        float ex[KC], su = 0.f;
#pragma unroll
        for (int k = 0; k < KC; k++) { ex[k] = expf(hsc[k * EE + t] - m); su += ex[k]; }
        float inv = 1.f / su, dd = 0.f;
#pragma unroll
        for (int k = 0; k < KC; k++) { float h = ex[k] * inv; hsc[k * EE + t] = h; dd += h; }
        rDd[t] = 1.f / sqrtf(dd);
    }
    __syncthreads();
    if (t < 64) {  // L = I - D^-1/2 H H^T
        int e = t >> 3, f = t & 7;
        float s = 0.f;
#pragma unroll
        for (int k = 0; k < KC; k++) s += hsc[k * EE + e] * hsc[k * EE + f];
        Lm[t] = ((e == f) ? 1.f : 0.f) - rDd[e] * s;
    }
    __syncthreads();
    {   // padded L @ clusters -> Bq (rows >= E zero)
        float lv[EE];
#pragma unroll
        for (int i = 0; i < EE; i++) {
            float s = 0.f;
#pragma unroll
            for (int f = 0; f < EE; f++) s += Lm[i * EE + f] * A[f * DIM + t];
            lv[i] = s;
        }
#pragma unroll
        for (int i = 0; i < EE; i++) Bq[i * DIM + t] = lv[i];
#pragma unroll
        for (int i = EE; i < KC; i++) Bq[i * DIM + t] = 0.f;
    }
    __syncthreads();
    mm16(Bq, nw, nb, Ck, t, 0);
    __syncthreads();
    mm16(Ck, m1w, m1b, Dv, t, 1);
    __syncthreads();
    mm16(Dv, m2w, m2b, A, t, 0);
    __syncthreads();
#pragma unroll
    for (int k = 0; k < KC; k++) g_c2[(size_t)b * KC * DIM + k * DIM + t] = A[k * DIM + t];
    if (t < 256) {  // partial norms
        int k = t >> 4, l = t & 15;
        float s = 0.f;
#pragma unroll
        for (int i = 0; i < 24; i++) {
            float v = A[k * DIM + l + 16 * i];
            s += v * v;
        }
        pna[t] = s;
    }
    __syncthreads();
    if (t < KC) {
        float s = 0.f;
#pragma unroll
        for (int l = 0; l < 16; l++) s += pna[t * 16 + l];
        nrm[t] = fmaxf(sqrtf(s), 1e-12f);
    }
    __syncthreads();
    if (t < 120) {  // cosine-sim mask, OR over batch
        int i = 0, rem = t, cnt = 15;
        while (rem >= cnt) { rem -= cnt; cnt--; i++; }
        int j = i + 1 + rem;
        float s = 0.f;
        for (int d = 0; d < DIM; d++) s += A[i * DIM + d] * A[j * DIM + d];
        if (s / (nrm[i] * nrm[j]) > 0.9f) atomicOr(&g_mask[i * 16 + j], 1u);
    }
}

// ---------------- sequential merge + gated fusion (block = batch) ----------------
__global__ __launch_bounds__(384) void merge_k(const float* __restrict__ fbw,
                                               const float* __restrict__ fbb,
                                               const float* __restrict__ fgw,
                                               const float* __restrict__ fgb) {
    __shared__ unsigned int msk[256];
    __shared__ float gsh[DIM];
    __shared__ float wsum[12];
    __shared__ float gate_s;
    int b = blockIdx.x, t = threadIdx.x;
    if (t < 256) msk[t] = g_mask[t];
    float c[KC];
#pragma unroll
    for (int k = 0; k < KC; k++) c[k] = g_c2[(size_t)b * KC * DIM + k * DIM + t];
    __syncthreads();
#pragma unroll
    for (int i = 0; i < KC; i++)
#pragma unroll
        for (int j = i + 1; j < KC; j++)
            if (msk[i * 16 + j]) {
                float m = (c[i] + c[j]) * 0.5f;
                c[i] = m;
                c[j] = m;
            }
    float g = 0.f;
#pragma unroll
    for (int k = 0; k < KC; k++) g += c[k];
    g *= (1.f / 16.f);
    gsh[t] = g;
    float p = g * fgw[t];
#pragma unroll
    for (int o = 16; o > 0; o >>= 1) p += __shfl_xor_sync(0xffffffffu, p, o);
    if ((t & 31) == 0) wsum[t >> 5] = p;
    __syncthreads();
    if (t == 0) {
        float s = 0.f;
#pragma unroll
        for (int i = 0; i < 12; i++) s += wsum[i];
        gate_s = 1.f / (1.f + expf(-(s + fgb[0])));
    }
    __syncthreads();
    float gate = gate_s;
    float acc = 0.f;
    for (int d = 0; d < DIM; d++) acc += gsh[d] * fbw[d * DIM + t];
    float fb = acc + fbb[t];
#pragma unroll
    for (int k = 0; k < KC; k++)
        g_flat[(size_t)b * KC * DIM + k * DIM + t] = c[k] + fb * gate;
}

// ---------------- classifier: [128,6144] @ [6144,1000], split-K ----------------
__global__ __launch_bounds__(256) void cls_k(const float* __restrict__ cw) {
    __shared__ float As[16][132];
    __shared__ float Bs[16][68];
    int bn = blockIdx.x * 64;
    int kz = blockIdx.z;
    int kbase = kz * (KC * DIM / KSPLIT);  // 768 per split
    int tid = threadIdx.x;
    int ty = tid >> 4, tx = tid & 15;
    float acc[8][4];
#pragma unroll
    for (int i = 0; i < 8; i++)
#pragma unroll
        for (int j = 0; j < 4; j++) acc[i][j] = 0.f;

    for (int k0 = kbase; k0 < kbase + 768; k0 += 16) {
#pragma unroll
        for (int l = 0; l < 2; l++) {
            int s = tid + l * 256;
            int row = s >> 2, kq = s & 3;
            float4 av = *(const float4*)&g_flat[(size_t)row * (KC * DIM) + k0 + kq * 4];
            As[kq * 4 + 0][row] = av.x;
            As[kq * 4 + 1][row] = av.y;
            As[kq * 4 + 2][row] = av.z;
            As[kq * 4 + 3][row] = av.w;
        }
#pragma unroll
        for (int j = 0; j < 4; j++) {
            int idx = tid * 4 + j;
            int row = idx >> 6, cc = idx & 63;
            int n = bn + cc;
            Bs[row][cc] = (n < NCLS) ? cw[(size_t)(k0 + row) * NCLS + n] : 0.f;
        }
        __syncthreads();
#pragma unroll
        for (int kk = 0; kk < 16; kk++) {
            float4 a0 = *(const float4*)&As[kk][ty * 8];
            float4 a1 = *(const float4*)&As[kk][ty * 8 + 4];
            float4 bb = *(const float4*)&Bs[kk][tx * 4];
            float av[8] = {a0.x, a0.y, a0.z, a0.w, a1.x, a1.y, a1.z, a1.w};
            float bv[4] = {bb.x, bb.y, bb.z, bb.w};
#pragma unroll
            for (int i = 0; i < 8; i++)
#pragma unroll
                for (int j = 0; j < 4; j++) acc[i][j] += av[i] * bv[j];
        }
        __syncthreads();
    }
    float* part = g_cpart + (size_t)kz * BATCH * NCLS;
#pragma unroll
    for (int i = 0; i < 8; i++)
#pragma unroll
        for (int j = 0; j < 4; j++) {
            int n = bn + tx * 4 + j;
            if (n < NCLS) part[(ty * 8 + i) * NCLS + n] = acc[i][j];
        }
}

__global__ void finout_k(const float* __restrict__ cb, float* __restrict__ out) {
    int idx = blockIdx.x * 256 + threadIdx.x;
    if (idx >= BATCH * NCLS) return;
    int n = idx % NCLS;
    float s = cb[n];
#pragma unroll
    for (int z = 0; z < KSPLIT; z++) s += g_cpart[(size_t)z * BATCH * NCLS + idx];
    out[idx] = s;
}

extern "C" void kernel_launch(void* const* d_in, const int* in_sizes, int n_in,
                              void* d_out, int out_size) {
    const float* x    = (const float*)d_in[0];
    const float* pw   = (const float*)d_in[1];
    const float* pb   = (const float*)d_in[2];
    const float* ln_g = (const float*)d_in[3];
    const float* ln_b = (const float*)d_in[4];
    const float* pos  = (const float*)d_in[5];
    const float* qw   = (const float*)d_in[6];
    const float* qb   = (const float*)d_in[7];
    const float* kw   = (const float*)d_in[8];
    const float* kb   = (const float*)d_in[9];
    const float* vw   = (const float*)d_in[10];
    const float* vb   = (const float*)d_in[11];
    const float* ew   = (const float*)d_in[12];
    const float* eb   = (const float*)d_in[13];
    const float* nw   = (const float*)d_in[14];
    const float* nb   = (const float*)d_in[15];
    const float* m1w  = (const float*)d_in[16];
    const float* m1b  = (const float*)d_in[17];
    const float* m2w  = (const float*)d_in[18];
    const float* m2b  = (const float*)d_in[19];
    const float* fbw  = (const float*)d_in[20];
    const float* fbb  = (const float*)d_in[21];
    const float* fgw  = (const float*)d_in[22];
    const float* fgb  = (const float*)d_in[23];
    const float* cw   = (const float*)d_in[24];
    const float* cb   = (const float*)d_in[25];
    float* out = (float*)d_out;

    cudaFuncSetAttribute(kmeans_k, cudaFuncAttributeMaxDynamicSharedMemorySize, 49152);
    cudaFuncSetAttribute(attn_k,   cudaFuncAttributeMaxDynamicSharedMemorySize, 98304);

    gemm_patch<<<dim3(3, 196), 256>>>(x, pw, pb);
    ln_k<<<BATCH * NPTS, 128>>>(ln_g, ln_b);
    kmeans_k<<<BATCH, 512, 49152>>>(pos);
    attn_k<<<BATCH, 384, 98304>>>(qw, qb, kw, kb, vw, vb, ew, eb, nw, nb,
                                  m1w, m1b, m2w, m2b);
    merge_k<<<BATCH, 384>>>(fbw, fbb, fgw, fgb);
    cls_k<<<dim3(16, 1, KSPLIT), 256>>>(cw);
    finout_k<<<(BATCH * NCLS + 255) / 256, 256>>>(cb, out);
}

// round 9
// speedup vs baseline: 1.2429x; 1.1036x over previous
#include <cuda_runtime.h>
#include <math.h>

#define BATCH 128
#define NPTS  196
#define PDIM  768
#define DIM   384
#define KC    16
#define EE    8
#define NITERS 10
#define NCLS  1000
#define KSPLIT 8
#define ROWS  (BATCH * KC)   // 2048

// ---------------- scratch (device globals; no allocation allowed) ----------------
__device__ float g_patches[BATCH * NPTS * DIM];
__device__ float g_pn[BATCH * NPTS * DIM];
__device__ float g_clusters[ROWS * DIM];
__device__ float g_q[ROWS * DIM];
__device__ float g_kk[ROWS * DIM];
__device__ float g_v[ROWS * DIM];
__device__ float g_mid[ROWS * DIM];
__device__ float g_t1[ROWS * DIM];
__device__ float g_t2[ROWS * DIM];
__device__ float g_c2[ROWS * DIM];
__device__ float g_flat[ROWS * DIM];
__device__ unsigned int g_mask[256];
__device__ float g_cpart[KSPLIT * BATCH * NCLS];

// ---------------- patch GEMM with fused im2col: [25088,768] @ [768,384] + pb ------
__global__ __launch_bounds__(256) void gemm_patch(const float* __restrict__ x,
                                                  const float* __restrict__ Bw,
                                                  const float* __restrict__ bias) {
    __shared__ float As[16][132];
    __shared__ float Bs[16][132];
    int bm = blockIdx.y * 128, bn = blockIdx.x * 128;
    int tid = threadIdx.x;
    int ty = tid >> 4, tx = tid & 15;

    int kqA = tid & 3;
    int rowA[2];
    size_t baseA[2];
#pragma unroll
    for (int l = 0; l < 2; l++) {
        rowA[l] = (tid >> 2) + l * 64;
        int r = bm + rowA[l];
        int b = r / 196;
        int n = r - b * 196;
        int hp = n / 14, wp = n - hp * 14;
        baseA[l] = ((size_t)(b * 3) * 224 + hp * 16) * 224 + wp * 16;
    }
    int rB0 = tid >> 5;
    int cB = (tid & 31) * 4;

    float4 aReg[2], bReg[2];
#pragma unroll
    for (int l = 0; l < 2; l++) {
        int k = kqA * 4;
        int c = k >> 8, ph = (k >> 4) & 15, pw = k & 15;
        aReg[l] = *(const float4*)&x[baseA[l] + (size_t)c * 50176 + ph * 224 + pw];
        bReg[l] = *(const float4*)&Bw[(size_t)(rB0 + l * 8) * DIM + bn + cB];
    }

    float acc[8][8];
#pragma unroll
    for (int i = 0; i < 8; i++)
#pragma unroll
        for (int j = 0; j < 8; j++) acc[i][j] = 0.f;

    for (int k0 = 0; k0 < PDIM; k0 += 16) {
#pragma unroll
        for (int l = 0; l < 2; l++) {
            As[kqA * 4 + 0][rowA[l]] = aReg[l].x;
            As[kqA * 4 + 1][rowA[l]] = aReg[l].y;
            As[kqA * 4 + 2][rowA[l]] = aReg[l].z;
            As[kqA * 4 + 3][rowA[l]] = aReg[l].w;
            *(float4*)&Bs[rB0 + l * 8][cB] = bReg[l];
        }
        __syncthreads();
        if (k0 + 16 < PDIM) {
            int kn = k0 + 16;
#pragma unroll
            for (int l = 0; l < 2; l++) {
                int k = kn + kqA * 4;
                int c = k >> 8, ph = (k >> 4) & 15, pw = k & 15;
                aReg[l] = *(const float4*)&x[baseA[l] + (size_t)c * 50176 + ph * 224 + pw];
                bReg[l] = *(const float4*)&Bw[(size_t)(kn + rB0 + l * 8) * DIM + bn + cB];
            }
        }
#pragma unroll
        for (int kk = 0; kk < 16; kk++) {
            float4 a0 = *(const float4*)&As[kk][ty * 4];
            float4 a1 = *(const float4*)&As[kk][64 + ty * 4];
            float4 b0 = *(const float4*)&Bs[kk][tx * 4];
            float4 b1 = *(const float4*)&Bs[kk][64 + tx * 4];
            float av[8] = {a0.x, a0.y, a0.z, a0.w, a1.x, a1.y, a1.z, a1.w};
            float bv[8] = {b0.x, b0.y, b0.z, b0.w, b1.x, b1.y, b1.z, b1.w};
#pragma unroll
            for (int i = 0; i < 8; i++)
#pragma unroll
                for (int j = 0; j < 8; j++) acc[i][j] += av[i] * bv[j];
        }
        __syncthreads();
    }

    int col0 = bn + tx * 4, col1 = bn + 64 + tx * 4;
    float4 bi0 = *(const float4*)&bias[col0];
    float4 bi1 = *(const float4*)&bias[col1];
#pragma unroll
    for (int i = 0; i < 8; i++) {
        int rowg = bm + ((i < 4) ? (ty * 4 + i) : (64 + ty * 4 + i - 4));
        float4 o0, o1;
        o0.x = acc[i][0] + bi0.x; o0.y = acc[i][1] + bi0.y;
        o0.z = acc[i][2] + bi0.z; o0.w = acc[i][3] + bi0.w;
        o1.x = acc[i][4] + bi1.x; o1.y = acc[i][5] + bi1.y;
        o1.z = acc[i][6] + bi1.z; o1.w = acc[i][7] + bi1.w;
        *(float4*)&g_patches[(size_t)rowg * DIM + col0] = o0;
        *(float4*)&g_patches[(size_t)rowg * DIM + col1] = o1;
    }
}

// ---------------- LayerNorm per row (384), 128 threads/row ----------------
__global__ void ln_k(const float* __restrict__ gam, const float* __restrict__ bet) {
    int r = blockIdx.x, t = threadIdx.x;
    const float* row = g_patches + (size_t)r * DIM;
    float v0 = row[t], v1 = row[t + 128], v2 = row[t + 256];
    float s = v0 + v1 + v2;
    float s2 = v0 * v0 + v1 * v1 + v2 * v2;
#pragma unroll
    for (int o = 16; o > 0; o >>= 1) {
        s += __shfl_xor_sync(0xffffffffu, s, o);
        s2 += __shfl_xor_sync(0xffffffffu, s2, o);
    }
    __shared__ float aa[4], bb[4];
    if ((t & 31) == 0) { aa[t >> 5] = s; bb[t >> 5] = s2; }
    __syncthreads();
    float su = aa[0] + aa[1] + aa[2] + aa[3];
    float sq = bb[0] + bb[1] + bb[2] + bb[3];
    float mu = su * (1.f / 384.f);
    float var = sq * (1.f / 384.f) - mu * mu;
    float rstd = 1.f / sqrtf(var + 1e-5f);
    float* o = g_pn + (size_t)r * DIM;
    o[t]       = (v0 - mu) * rstd * gam[t]       + bet[t];
    o[t + 128] = (v1 - mu) * rstd * gam[t + 128] + bet[t + 128];
    o[t + 256] = (v2 - mu) * rstd * gam[t + 256] + bet[t + 256];
}

// ---------------- k-means: 10 iterations, one block per batch ----------------
__global__ __launch_bounds__(512) void kmeans_k(const float* __restrict__ pos) {
    extern __shared__ float sm[];
    float* centers = sm;
    float* accum   = sm + KC * DIM;
    __shared__ int   asgn[NPTS];
    __shared__ int   scnt[KC];
    __shared__ float csq[KC];
    int b = blockIdx.x, t = threadIdx.x;
    const float* pnb = g_pn + (size_t)b * NPTS * DIM;

    if (b == 0 && t < 256) g_mask[t] = 0u;

    for (int e = t; e < KC * DIM; e += 512) {
        int k = e / DIM, d = e - k * DIM;
        centers[e] = pnb[(13 * k) * DIM + d];
    }
    __syncthreads();

    for (int iter = 0; iter < NITERS; ++iter) {
        {
            int w = t >> 5, lane = t & 31;
            float p = 0.f;
#pragma unroll
            for (int i = 0; i < 12; i++) {
                float cv = centers[w * DIM + lane + 32 * i];
                p += cv * cv;
            }
#pragma unroll
            for (int o = 16; o > 0; o >>= 1) p += __shfl_xor_sync(0xffffffffu, p, o);
            if (lane == 0) csq[w] = p;
        }
        __syncthreads();
        if (t < 224) {
            int tt = (t < 196) ? t : 195;
            int g = tt >> 2, q = tt & 3;
            int p0 = 4 * g;
            int fb = q * 24;
            float acc[4][KC];
#pragma unroll
            for (int p = 0; p < 4; p++)
#pragma unroll
                for (int k = 0; k < KC; k++) acc[p][k] = 0.f;
            const float4* pn4 = (const float4*)pnb;
            const float4* c4  = (const float4*)centers;
            for (int i = 0; i < 24; i++) {
                float4 v0 = pn4[(p0 + 0) * 96 + fb + i];
                float4 v1 = pn4[(p0 + 1) * 96 + fb + i];
                float4 v2 = pn4[(p0 + 2) * 96 + fb + i];
                float4 v3 = pn4[(p0 + 3) * 96 + fb + i];
#pragma unroll
                for (int k = 0; k < KC; k++) {
                    float4 c = c4[k * 96 + fb + i];
                    acc[0][k] += v0.x * c.x + v0.y * c.y + v0.z * c.z + v0.w * c.w;
                    acc[1][k] += v1.x * c.x + v1.y * c.y + v1.z * c.z + v1.w * c.w;
                    acc[2][k] += v2.x * c.x + v2.y * c.y + v2.z * c.z + v2.w * c.w;
                    acc[3][k] += v3.x * c.x + v3.y * c.y + v3.z * c.z + v3.w * c.w;
                }
            }
#pragma unroll
            for (int p = 0; p < 4; p++)
#pragma unroll
                for (int k = 0; k < KC; k++) {
                    float r = acc[p][k];
                    r += __shfl_xor_sync(0xffffffffu, r, 1);
                    r += __shfl_xor_sync(0xffffffffu, r, 2);
                    acc[p][k] = r;
                }
            if (q == 0 && t < 196) {
#pragma unroll
                for (int p = 0; p < 4; p++) {
                    float best = csq[0] - 2.f * acc[p][0];
                    int bi = 0;
#pragma unroll
                    for (int k = 1; k < KC; k++) {
                        float scv = csq[k] - 2.f * acc[p][k];
                        if (scv < best) { best = scv; bi = k; }
                    }
                    asgn[p0 + p] = bi;
                }
            }
        }
        for (int e = t; e < KC * DIM; e += 512) accum[e] = 0.f;
        if (t < KC) scnt[t] = 0;
        __syncthreads();
        if (t < DIM) {
            for (int n = 0; n < NPTS; n++)
                accum[asgn[n] * DIM + t] += pnb[n * DIM + t];
        }
        if (t < NPTS) atomicAdd(&scnt[asgn[t]], 1);
        __syncthreads();
        float newc[KC];
        if (t < DIM) {
#pragma unroll
            for (int k = 0; k < KC; k++) {
                int c = scnt[k];
                newc[k] = (c > 0) ? (accum[k * DIM + t] / (float)c) : centers[k * DIM + t];
            }
        }
        __syncthreads();
        if (t < DIM) {
#pragma unroll
            for (int k = 0; k < KC; k++) centers[k * DIM + t] = newc[k];
        }
        __syncthreads();
    }
    for (int e = t; e < KC * DIM; e += 512)
        g_clusters[(size_t)b * KC * DIM + e] = centers[e] + pos[e];
}

// ---------------- generic 64x64-tile GEMM body: C = A[ROWS,384]@W[384,64..] -------
__device__ __forceinline__ void gemm64_body(const float* __restrict__ A,
                                            const float* __restrict__ W,
                                            const float* __restrict__ bias,
                                            float* __restrict__ C,
                                            int bm, int bn, int wcol, int gelu) {
    __shared__ float As[16][68];
    __shared__ float Bs[16][68];
    int tid = threadIdx.x;
    int ty = tid >> 4, tx = tid & 15;
    int rowA = tid >> 2, kqA = (tid & 3) * 4;
    int rB = tid >> 4, cB = (tid & 15) * 4;

    float4 aReg = *(const float4*)&A[(size_t)(bm + rowA) * DIM + kqA];
    float4 bReg = *(const float4*)&W[(size_t)rB * DIM + wcol + cB];

    float acc[4][4];
#pragma unroll
    for (int i = 0; i < 4; i++)
#pragma unroll
        for (int j = 0; j < 4; j++) acc[i][j] = 0.f;

    for (int k0 = 0; k0 < DIM; k0 += 16) {
        As[kqA + 0][rowA] = aReg.x;
        As[kqA + 1][rowA] = aReg.y;
        As[kqA + 2][rowA] = aReg.z;
        As[kqA + 3][rowA] = aReg.w;
        *(float4*)&Bs[rB][cB] = bReg;
        __syncthreads();
        if (k0 + 16 < DIM) {
            aReg = *(const float4*)&A[(size_t)(bm + rowA) * DIM + k0 + 16 + kqA];
            bReg = *(const float4*)&W[(size_t)(k0 + 16 + rB) * DIM + wcol + cB];
        }
#pragma unroll
        for (int kk = 0; kk < 16; kk++) {
            float4 a = *(const float4*)&As[kk][ty * 4];
            float4 bsv = *(const float4*)&Bs[kk][tx * 4];
            float av[4] = {a.x, a.y, a.z, a.w};
            float bv[4] = {bsv.x, bsv.y, bsv.z, bsv.w};
#pragma unroll
            for (int i = 0; i < 4; i++)
#pragma unroll
                for (int j = 0; j < 4; j++) acc[i][j] += av[i] * bv[j];
        }
        __syncthreads();
    }
    float4 bi = *(const float4*)&bias[wcol + tx * 4];
    float bvv[4] = {bi.x, bi.y, bi.z, bi.w};
#pragma unroll
    for (int i = 0; i < 4; i++) {
        int rowg = bm + ty * 4 + i;
        float4 o;
        float v[4];
#pragma unroll
        for (int j = 0; j < 4; j++) {
            float u = acc[i][j] + bvv[j];
            if (gelu) u = 0.5f * u * (1.f + erff(u * 0.70710678118654752f));
            v[j] = u;
        }
        o.x = v[0]; o.y = v[1]; o.z = v[2]; o.w = v[3];
        *(float4*)&C[(size_t)rowg * DIM + bn + tx * 4] = o;
    }
}

// QKV: grid (18, 32); col blocks 0-5 -> Q, 6-11 -> K, 12-17 -> V
__global__ __launch_bounds__(256) void qkv_k(
    const float* __restrict__ qw, const float* __restrict__ qb,
    const float* __restrict__ kw, const float* __restrict__ kb,
    const float* __restrict__ vw, const float* __restrict__ vb) {
    int nb = blockIdx.x;
    const float* W; const float* bias; float* out;
    if (nb < 6)       { W = qw; bias = qb; out = g_q; }
    else if (nb < 12) { W = kw; bias = kb; out = g_kk; nb -= 6; }
    else              { W = vw; bias = vb; out = g_v;  nb -= 12; }
    gemm64_body(g_clusters, W, bias, out, blockIdx.y * 64, nb * 64, nb * 64, 0);
}

// MLP chain: mode 0: g_mid@nw->g_t1; 1: g_t1@m1w(+gelu)->g_t2; 2: g_t2@m2w->g_c2
__global__ __launch_bounds__(256) void mlp_k(const float* __restrict__ W,
                                             const float* __restrict__ bias,
                                             int mode) {
    const float* A = (mode == 0) ? g_mid : (mode == 1) ? g_t1 : g_t2;
    float* C = (mode == 0) ? g_t1 : (mode == 1) ? g_t2 : g_c2;
    int bn = blockIdx.x * 64;
    gemm64_body(A, W, bias, C, blockIdx.y * 64, bn, bn, (mode == 1) ? 1 : 0);
}

// ---------------- attention middle: scores/softmax/AV/hypergraph/L@AV -------------
__global__ __launch_bounds__(384) void attn_mid_k(const float* __restrict__ ew,
                                                  const float* __restrict__ eb) {
    extern __shared__ float sm[];
    float* Qs = sm;            // 16x384 (reused as AV)
    float* Ks = sm + 6144;
    float* Vs = sm + 12288;
    __shared__ float sc[256];
    __shared__ float hsc[KC * EE];
    __shared__ float rDd[EE];
    __shared__ float Lm[EE * EE];
    int b = blockIdx.x, t = threadIdx.x;
    size_t base = (size_t)b * KC * DIM;

#pragma unroll
    for (int k = 0; k < KC; k++) {
        Qs[k * DIM + t] = g_q[base + k * DIM + t];
        Ks[k * DIM + t] = g_kk[base + k * DIM + t];
        Vs[k * DIM + t] = g_v[base + k * DIM + t];
    }
    __syncthreads();
    if (t < 256) {
        int q = t >> 4, kk = t & 15;
        const float4* Q4 = (const float4*)Qs;
        const float4* K4 = (const float4*)Ks;
        float s = 0.f;
        for (int i = 0; i < 96; i++) {
            float4 a = Q4[q * 96 + i];
            float4 c = K4[kk * 96 + i];
            s += a.x * c.x + a.y * c.y + a.z * c.z + a.w * c.w;
        }
        sc[t] = s * 0.05103103630798288f;
    }
    __syncthreads();
    if (t < KC) {
        float m = -1e30f;
#pragma unroll
        for (int k = 0; k < KC; k++) m = fmaxf(m, sc[t * 16 + k]);
        float e[KC], su = 0.f;
#pragma unroll
        for (int k = 0; k < KC; k++) { e[k] = expf(sc[t * 16 + k] - m); su += e[k]; }
        float inv = 1.f / su;
#pragma unroll
        for (int k = 0; k < KC; k++) sc[t * 16 + k] = e[k] * inv;
    }
    __syncthreads();
    {
        float nv[KC];
#pragma unroll
        for (int q = 0; q < KC; q++) {
            float s = 0.f;
#pragma unroll
            for (int k = 0; k < KC; k++) s += sc[q * 16 + k] * Vs[k * DIM + t];
            nv[q] = s;
        }
        __syncthreads();
#pragma unroll
        for (int q = 0; q < KC; q++) Qs[q * DIM + t] = nv[q];   // AV
    }
    __syncthreads();
    if (t < 128) {
        int k = t >> 3, e = t & 7;
        float s = 0.f;
        for (int d = 0; d < DIM; d++) s += Qs[k * DIM + d] * ew[d * EE + e];
        hsc[k * EE + e] = s + eb[e];
    }
    __syncthreads();
    if (t < EE) {
        float m = -1e30f;
#pragma unroll
        for (int k = 0; k < KC; k++) m = fmaxf(m, hsc[k * EE + t]);
        float ex[KC], su = 0.f;
#pragma unroll
        for (int k = 0; k < KC; k++) { ex[k] = expf(hsc[k * EE + t] - m); su += ex[k]; }
        float inv = 1.f / su, dd = 0.f;
#pragma unroll
        for (int k = 0; k < KC; k++) { float h = ex[k] * inv; hsc[k * EE + t] = h; dd += h; }
        rDd[t] = 1.f / sqrtf(dd);
    }
    __syncthreads();
    if (t < 64) {
        int e = t >> 3, f = t & 7;
        float s = 0.f;
#pragma unroll
        for (int k = 0; k < KC; k++) s += hsc[k * EE + e] * hsc[k * EE + f];
        Lm[t] = ((e == f) ? 1.f : 0.f) - rDd[e] * s;
    }
    __syncthreads();
    {
        float lv[EE];
#pragma unroll
        for (int i = 0; i < EE; i++) {
            float s = 0.f;
#pragma unroll
            for (int f = 0; f < EE; f++) s += Lm[i * EE + f] * Qs[f * DIM + t];
            lv[i] = s;
        }
#pragma unroll
        for (int i = 0; i < EE; i++) g_mid[base + i * DIM + t] = lv[i];
#pragma unroll
        for (int i = EE; i < KC; i++) g_mid[base + i * DIM + t] = 0.f;
    }
}

// ---------------- cosine-similarity mask over batch ----------------
__global__ __launch_bounds__(384) void mask_k() {
    __shared__ float A[KC * DIM];
    __shared__ float pna[256];
    __shared__ float nrm[KC];
    int b = blockIdx.x, t = threadIdx.x;
    size_t base = (size_t)b * KC * DIM;
#pragma unroll
    for (int k = 0; k < KC; k++) A[k * DIM + t] = g_c2[base + k * DIM + t];
    __syncthreads();
    if (t < 256) {
        int k = t >> 4, l = t & 15;
        float s = 0.f;
#pragma unroll
        for (int i = 0; i < 24; i++) {
            float v = A[k * DIM + l + 16 * i];
            s += v * v;
        }
        pna[t] = s;
    }
    __syncthreads();
    if (t < KC) {
        float s = 0.f;
#pragma unroll
        for (int l = 0; l < 16; l++) s += pna[t * 16 + l];
        nrm[t] = fmaxf(sqrtf(s), 1e-12f);
    }
    __syncthreads();
    if (t < 120) {
        int i = 0, rem = t, cnt = 15;
        while (rem >= cnt) { rem -= cnt; cnt--; i++; }
        int j = i + 1 + rem;
        float s = 0.f;
        for (int d = 0; d < DIM; d++) s += A[i * DIM + d] * A[j * DIM + d];
        if (s / (nrm[i] * nrm[j]) > 0.9f) atomicOr(&g_mask[i * 16 + j], 1u);
    }
}

// ---------------- sequential merge + gated fusion (block = batch) ----------------
__global__ __launch_bounds__(384) void merge_k(const float* __restrict__ fbw,
                                               const float* __restrict__ fbb,
                                               const float* __restrict__ fgw,
                                               const float* __restrict__ fgb) {
    __shared__ unsigned int msk[256];
    __shared__ float gsh[DIM];
    __shared__ float wsum[12];
    __shared__ float gate_s;
    int b = blockIdx.x, t = threadIdx.x;
    if (t < 256) msk[t] = g_mask[t];
    float c[KC];
#pragma unroll
    for (int k = 0; k < KC; k++) c[k] = g_c2[(size_t)b * KC * DIM + k * DIM + t];
    __syncthreads();
#pragma unroll
    for (int i = 0; i < KC; i++)
#pragma unroll
        for (int j = i + 1; j < KC; j++)
            if (msk[i * 16 + j]) {
                float m = (c[i] + c[j]) * 0.5f;
                c[i] = m;
                c[j] = m;
            }
    float g = 0.f;
#pragma unroll
    for (int k = 0; k < KC; k++) g += c[k];
    g *= (1.f / 16.f);
    gsh[t] = g;
    float p = g * fgw[t];
#pragma unroll
    for (int o = 16; o > 0; o >>= 1) p += __shfl_xor_sync(0xffffffffu, p, o);
    if ((t & 31) == 0) wsum[t >> 5] = p;
    __syncthreads();
    if (t == 0) {
        float s = 0.f;
#pragma unroll
        for (int i = 0; i < 12; i++) s += wsum[i];
        gate_s = 1.f / (1.f + expf(-(s + fgb[0])));
    }
    __syncthreads();
    float gate = gate_s;
    float acc = 0.f;
    for (int d = 0; d < DIM; d++) acc += gsh[d] * fbw[d * DIM + t];
    float fb = acc + fbb[t];
#pragma unroll
    for (int k = 0; k < KC; k++)
        g_flat[(size_t)b * KC * DIM + k * DIM + t] = c[k] + fb * gate;
}

// ---------------- classifier: [128,6144] @ [6144,1000], split-K ----------------
__global__ __launch_bounds__(256) void cls_k(const float* __restrict__ cw) {
    __shared__ float As[16][132];
    __shared__ float Bs[16][68];
    int bn = blockIdx.x * 64;
    int kz = blockIdx.z;
    int kbase = kz * (KC * DIM / KSPLIT);
    int tid = threadIdx.x;
    int ty = tid >> 4, tx = tid & 15;
    float acc[8][4];
#pragma unroll
    for (int i = 0; i < 8; i++)
#pragma unroll
        for (int j = 0; j < 4; j++) acc[i][j] = 0.f;

    for (int k0 = kbase; k0 < kbase + 768; k0 += 16) {
#pragma unroll
        for (int l = 0; l < 2; l++) {
            int s = tid + l * 256;
            int row = s >> 2, kq = s & 3;
            float4 av = *(const float4*)&g_flat[(size_t)row * (KC * DIM) + k0 + kq * 4];
            As[kq * 4 + 0][row] = av.x;
            As[kq * 4 + 1][row] = av.y;
            As[kq * 4 + 2][row] = av.z;
            As[kq * 4 + 3][row] = av.w;
        }
#pragma unroll
        for (int j = 0; j < 4; j++) {
            int idx = tid * 4 + j;
            int row = idx >> 6, cc = idx & 63;
            int n = bn + cc;
            Bs[row][cc] = (n < NCLS) ? cw[(size_t)(k0 + row) * NCLS + n] : 0.f;
        }
        __syncthreads();
#pragma unroll
        for (int kk = 0; kk < 16; kk++) {
            float4 a0 = *(const float4*)&As[kk][ty * 8];
            float4 a1 = *(const float4*)&As[kk][ty * 8 + 4];
            float4 bb = *(const float4*)&Bs[kk][tx * 4];
            float av[8] = {a0.x, a0.y, a0.z, a0.w, a1.x, a1.y, a1.z, a1.w};
            float bv[4] = {bb.x, bb.y, bb.z, bb.w};
#pragma unroll
            for (int i = 0; i < 8; i++)
#pragma unroll
                for (int j = 0; j < 4; j++) acc[i][j] += av[i] * bv[j];
        }
        __syncthreads();
    }
    float* part = g_cpart + (size_t)kz * BATCH * NCLS;
#pragma unroll
    for (int i = 0; i < 8; i++)
#pragma unroll
        for (int j = 0; j < 4; j++) {
            int n = bn + tx * 4 + j;
            if (n < NCLS) part[(ty * 8 + i) * NCLS + n] = acc[i][j];
        }
}

__global__ void finout_k(const float* __restrict__ cb, float* __restrict__ out) {
    int idx = blockIdx.x * 256 + threadIdx.x;
    if (idx >= BATCH * NCLS) return;
    int n = idx % NCLS;
    float s = cb[n];
#pragma unroll
    for (int z = 0; z < KSPLIT; z++) s += g_cpart[(size_t)z * BATCH * NCLS + idx];
    out[idx] = s;
}

extern "C" void kernel_launch(void* const* d_in, const int* in_sizes, int n_in,
                              void* d_out, int out_size) {
    const float* x    = (const float*)d_in[0];
    const float* pw   = (const float*)d_in[1];
    const float* pb   = (const float*)d_in[2];
    const float* ln_g = (const float*)d_in[3];
    const float* ln_b = (const float*)d_in[4];
    const float* pos  = (const float*)d_in[5];
    const float* qw   = (const float*)d_in[6];
    const float* qb   = (const float*)d_in[7];
    const float* kw   = (const float*)d_in[8];
    const float* kb   = (const float*)d_in[9];
    const float* vw   = (const float*)d_in[10];
    const float* vb   = (const float*)d_in[11];
    const float* ew   = (const float*)d_in[12];
    const float* eb   = (const float*)d_in[13];
    const float* nw   = (const float*)d_in[14];
    const float* nb   = (const float*)d_in[15];
    const float* m1w  = (const float*)d_in[16];
    const float* m1b  = (const float*)d_in[17];
    const float* m2w  = (const float*)d_in[18];
    const float* m2b  = (const float*)d_in[19];
    const float* fbw  = (const float*)d_in[20];
    const float* fbb  = (const float*)d_in[21];
    const float* fgw  = (const float*)d_in[22];
    const float* fgb  = (const float*)d_in[23];
    const float* cw   = (const float*)d_in[24];
    const float* cb   = (const float*)d_in[25];
    float* out = (float*)d_out;

    cudaFuncSetAttribute(kmeans_k,   cudaFuncAttributeMaxDynamicSharedMemorySize, 49152);
    cudaFuncSetAttribute(attn_mid_k, cudaFuncAttributeMaxDynamicSharedMemorySize, 73728);

    gemm_patch<<<dim3(3, 196), 256>>>(x, pw, pb);
    ln_k<<<BATCH * NPTS, 128>>>(ln_g, ln_b);
    kmeans_k<<<BATCH, 512, 49152>>>(pos);
    qkv_k<<<dim3(18, 32), 256>>>(qw, qb, kw, kb, vw, vb);
    attn_mid_k<<<BATCH, 384, 73728>>>(ew, eb);
    mlp_k<<<dim3(6, 32), 256>>>(nw, nb, 0);
    mlp_k<<<dim3(6, 32), 256>>>(m1w, m1b, 1);
    mlp_k<<<dim3(6, 32), 256>>>(m2w, m2b, 2);
    mask_k<<<BATCH, 384>>>();
    merge_k<<<BATCH, 384>>>(fbw, fbb, fgw, fgb);
    cls_k<<<dim3(16, 1, KSPLIT), 256>>>(cw);
    finout_k<<<(BATCH * NCLS + 255) / 256, 256>>>(cb, out);
}

// round 10
// speedup vs baseline: 1.2584x; 1.0125x over previous
#include <cuda_runtime.h>
#include <math.h>

#define BATCH 128
#define NPTS  196
#define PDIM  768
#define DIM   384
#define KC    16
#define EE    8
#define NITERS 10
#define NCLS  1000
#define KSPLIT 8
#define ROWS  (BATCH * KC)   // 2048

// ---------------- scratch (device globals; no allocation allowed) ----------------
__device__ float g_patches[BATCH * NPTS * DIM];
__device__ float g_pn[BATCH * NPTS * DIM];
__device__ float g_clusters[ROWS * DIM];
__device__ float g_q[ROWS * DIM];
__device__ float g_kk[ROWS * DIM];
__device__ float g_v[ROWS * DIM];
__device__ float g_mid[ROWS * DIM];
__device__ float g_t1[ROWS * DIM];
__device__ float g_t2[ROWS * DIM];
__device__ float g_c2[ROWS * DIM];
__device__ float g_flat[ROWS * DIM];
__device__ unsigned int g_mask[256];
__device__ float g_cpart[KSPLIT * BATCH * NCLS];

// ------- patch GEMM with fused im2col: [25088,768] @ [768,384] + pb --------------
// BM=256, BN=128, BK=16, 256 threads, 16x8 microtile (4x 64-row groups, 2x 64-col)
__global__ __launch_bounds__(256) void gemm_patch(const float* __restrict__ x,
                                                  const float* __restrict__ Bw,
                                                  const float* __restrict__ bias) {
    __shared__ float As[16][260];
    __shared__ float Bs[16][132];
    int bm = blockIdx.y * 256, bn = blockIdx.x * 128;
    int tid = threadIdx.x;
    int ty = tid >> 4, tx = tid & 15;

    // A loader: 4 rows per thread, one k-quad
    int kqA = (tid & 3) * 4;
    int rowA[4];
    size_t baseA[4];
#pragma unroll
    for (int l = 0; l < 4; l++) {
        rowA[l] = (tid >> 2) + l * 64;
        int r = bm + rowA[l];
        int b = r / 196;
        int n = r - b * 196;
        int hp = n / 14, wp = n - hp * 14;
        baseA[l] = ((size_t)(b * 3) * 224 + hp * 16) * 224 + wp * 16;
    }
    // B loader: 2 float4 per thread
    int rB = tid >> 5;            // 0..7
    int cB = (tid & 31) * 4;      // 0..124

    float4 aReg[4], bReg[2];
#pragma unroll
    for (int l = 0; l < 4; l++) {
        int k = kqA;
        int c = k >> 8, ph = (k >> 4) & 15, pw = k & 15;
        aReg[l] = *(const float4*)&x[baseA[l] + (size_t)c * 50176 + ph * 224 + pw];
    }
#pragma unroll
    for (int l = 0; l < 2; l++)
        bReg[l] = *(const float4*)&Bw[(size_t)(rB + l * 8) * DIM + bn + cB];

    float acc[16][8];
#pragma unroll
    for (int i = 0; i < 16; i++)
#pragma unroll
        for (int j = 0; j < 8; j++) acc[i][j] = 0.f;

    for (int k0 = 0; k0 < PDIM; k0 += 16) {
#pragma unroll
        for (int l = 0; l < 4; l++) {
            As[kqA + 0][rowA[l]] = aReg[l].x;
            As[kqA + 1][rowA[l]] = aReg[l].y;
            As[kqA + 2][rowA[l]] = aReg[l].z;
            As[kqA + 3][rowA[l]] = aReg[l].w;
        }
#pragma unroll
        for (int l = 0; l < 2; l++)
            *(float4*)&Bs[rB + l * 8][cB] = bReg[l];
        __syncthreads();
        if (k0 + 16 < PDIM) {
            int kn = k0 + 16;
#pragma unroll
            for (int l = 0; l < 4; l++) {
                int k = kn + kqA;
                int c = k >> 8, ph = (k >> 4) & 15, pw = k & 15;
                aReg[l] = *(const float4*)&x[baseA[l] + (size_t)c * 50176 + ph * 224 + pw];
            }
#pragma unroll
            for (int l = 0; l < 2; l++)
                bReg[l] = *(const float4*)&Bw[(size_t)(kn + rB + l * 8) * DIM + bn + cB];
        }
#pragma unroll
        for (int kk = 0; kk < 16; kk++) {
            float4 a0 = *(const float4*)&As[kk][ty * 4];
            float4 a1 = *(const float4*)&As[kk][64 + ty * 4];
            float4 a2 = *(const float4*)&As[kk][128 + ty * 4];
            float4 a3 = *(const float4*)&As[kk][192 + ty * 4];
            float4 b0 = *(const float4*)&Bs[kk][tx * 4];
            float4 b1 = *(const float4*)&Bs[kk][64 + tx * 4];
            float av[16] = {a0.x, a0.y, a0.z, a0.w, a1.x, a1.y, a1.z, a1.w,
                            a2.x, a2.y, a2.z, a2.w, a3.x, a3.y, a3.z, a3.w};
            float bv[8] = {b0.x, b0.y, b0.z, b0.w, b1.x, b1.y, b1.z, b1.w};
#pragma unroll
            for (int i = 0; i < 16; i++)
#pragma unroll
                for (int j = 0; j < 8; j++) acc[i][j] += av[i] * bv[j];
        }
        __syncthreads();
    }

    float4 bi0 = *(const float4*)&bias[bn + tx * 4];
    float4 bi1 = *(const float4*)&bias[bn + 64 + tx * 4];
    float bb0[4] = {bi0.x, bi0.y, bi0.z, bi0.w};
    float bb1[4] = {bi1.x, bi1.y, bi1.z, bi1.w};
#pragma unroll
    for (int i = 0; i < 16; i++) {
        int rowg = bm + (i >> 2) * 64 + ty * 4 + (i & 3);
        float4 o0, o1;
        o0.x = acc[i][0] + bb0[0]; o0.y = acc[i][1] + bb0[1];
        o0.z = acc[i][2] + bb0[2]; o0.w = acc[i][3] + bb0[3];
        o1.x = acc[i][4] + bb1[0]; o1.y = acc[i][5] + bb1[1];
        o1.z = acc[i][6] + bb1[2]; o1.w = acc[i][7] + bb1[3];
        *(float4*)&g_patches[(size_t)rowg * DIM + bn + tx * 4] = o0;
        *(float4*)&g_patches[(size_t)rowg * DIM + bn + 64 + tx * 4] = o1;
    }
}

// ---------------- LayerNorm per row (384), 128 threads/row ----------------
__global__ void ln_k(const float* __restrict__ gam, const float* __restrict__ bet) {
    int r = blockIdx.x, t = threadIdx.x;
    const float* row = g_patches + (size_t)r * DIM;
    float v0 = row[t], v1 = row[t + 128], v2 = row[t + 256];
    float s = v0 + v1 + v2;
    float s2 = v0 * v0 + v1 * v1 + v2 * v2;
#pragma unroll
    for (int o = 16; o > 0; o >>= 1) {
        s += __shfl_xor_sync(0xffffffffu, s, o);
        s2 += __shfl_xor_sync(0xffffffffu, s2, o);
    }
    __shared__ float aa[4], bb[4];
    if ((t & 31) == 0) { aa[t >> 5] = s; bb[t >> 5] = s2; }
    __syncthreads();
    float su = aa[0] + aa[1] + aa[2] + aa[3];
    float sq = bb[0] + bb[1] + bb[2] + bb[3];
    float mu = su * (1.f / 384.f);
    float var = sq * (1.f / 384.f) - mu * mu;
    float rstd = 1.f / sqrtf(var + 1e-5f);
    float* o = g_pn + (size_t)r * DIM;
    o[t]       = (v0 - mu) * rstd * gam[t]       + bet[t];
    o[t + 128] = (v1 - mu) * rstd * gam[t + 128] + bet[t + 128];
    o[t + 256] = (v2 - mu) * rstd * gam[t + 256] + bet[t + 256];
}

// ---------------- k-means: 10 iterations, one block per batch ----------------
__global__ __launch_bounds__(512) void kmeans_k(const float* __restrict__ pos) {
    extern __shared__ float sm[];
    float* centers = sm;
    float* accum   = sm + KC * DIM;
    __shared__ int   asgn[NPTS];
    __shared__ int   scnt[KC];
    __shared__ float csq[KC];
    int b = blockIdx.x, t = threadIdx.x;
    const float* pnb = g_pn + (size_t)b * NPTS * DIM;

    if (b == 0 && t < 256) g_mask[t] = 0u;

    for (int e = t; e < KC * DIM; e += 512) {
        int k = e / DIM, d = e - k * DIM;
        centers[e] = pnb[(13 * k) * DIM + d];
    }
    __syncthreads();

    for (int iter = 0; iter < NITERS; ++iter) {
        {
            int w = t >> 5, lane = t & 31;
            float p = 0.f;
#pragma unroll
            for (int i = 0; i < 12; i++) {
                float cv = centers[w * DIM + lane + 32 * i];
                p += cv * cv;
            }
#pragma unroll
            for (int o = 16; o > 0; o >>= 1) p += __shfl_xor_sync(0xffffffffu, p, o);
            if (lane == 0) csq[w] = p;
        }
        __syncthreads();
        if (t < 224) {
            int tt = (t < 196) ? t : 195;
            int g = tt >> 2, q = tt & 3;
            int p0 = 4 * g;
            int fb = q * 24;
            float acc[4][KC];
#pragma unroll
            for (int p = 0; p < 4; p++)
#pragma unroll
                for (int k = 0; k < KC; k++) acc[p][k] = 0.f;
            const float4* pn4 = (const float4*)pnb;
            const float4* c4  = (const float4*)centers;
            for (int i = 0; i < 24; i++) {
                float4 v0 = pn4[(p0 + 0) * 96 + fb + i];
                float4 v1 = pn4[(p0 + 1) * 96 + fb + i];
                float4 v2 = pn4[(p0 + 2) * 96 + fb + i];
                float4 v3 = pn4[(p0 + 3) * 96 + fb + i];
#pragma unroll
                for (int k = 0; k < KC; k++) {
                    float4 c = c4[k * 96 + fb + i];
                    acc[0][k] += v0.x * c.x + v0.y * c.y + v0.z * c.z + v0.w * c.w;
                    acc[1][k] += v1.x * c.x + v1.y * c.y + v1.z * c.z + v1.w * c.w;
                    acc[2][k] += v2.x * c.x + v2.y * c.y + v2.z * c.z + v2.w * c.w;
                    acc[3][k] += v3.x * c.x + v3.y * c.y + v3.z * c.z + v3.w * c.w;
                }
            }
#pragma unroll
            for (int p = 0; p < 4; p++)
#pragma unroll
                for (int k = 0; k < KC; k++) {
                    float r = acc[p][k];
                    r += __shfl_xor_sync(0xffffffffu, r, 1);
                    r += __shfl_xor_sync(0xffffffffu, r, 2);
                    acc[p][k] = r;
                }
            if (q == 0 && t < 196) {
#pragma unroll
                for (int p = 0; p < 4; p++) {
                    float best = csq[0] - 2.f * acc[p][0];
                    int bi = 0;
#pragma unroll
                    for (int k = 1; k < KC; k++) {
                        float scv = csq[k] - 2.f * acc[p][k];
                        if (scv < best) { best = scv; bi = k; }
                    }
                    asgn[p0 + p] = bi;
                }
            }
        }
        for (int e = t; e < KC * DIM; e += 512) accum[e] = 0.f;
        if (t < KC) scnt[t] = 0;
        __syncthreads();
        if (t < DIM) {
            for (int n = 0; n < NPTS; n++)
                accum[asgn[n] * DIM + t] += pnb[n * DIM + t];
        }
        if (t < NPTS) atomicAdd(&scnt[asgn[t]], 1);
        __syncthreads();
        float newc[KC];
        if (t < DIM) {
#pragma unroll
            for (int k = 0; k < KC; k++) {
                int c = scnt[k];
                newc[k] = (c > 0) ? (accum[k * DIM + t] / (float)c) : centers[k * DIM + t];
            }
        }
        __syncthreads();
        if (t < DIM) {
#pragma unroll
            for (int k = 0; k < KC; k++) centers[k * DIM + t] = newc[k];
        }
        __syncthreads();
    }
    for (int e = t; e < KC * DIM; e += 512)
        g_clusters[(size_t)b * KC * DIM + e] = centers[e] + pos[e];
}

// ------- 64x128-tile GEMM body, 128 threads, 8x8 microtile (A rows broadcast) -----
__device__ __forceinline__ void gemm64x128(const float* __restrict__ A,
                                           const float* __restrict__ W,
                                           const float* __restrict__ bias,
                                           float* __restrict__ C,
                                           int bm, int wcol, int gelu) {
    __shared__ float As[16][68];
    __shared__ float Bs[16][132];
    int tid = threadIdx.x;
    int ty = tid >> 4, tx = tid & 15;   // ty 0..7, tx 0..15

    int rowA = tid >> 2;                // 0..31
    int kqA = (tid & 3) * 4;
    int rB = tid >> 5;                  // 0..3
    int cB = (tid & 31) * 4;            // 0..124

    float4 aReg[2], bReg[4];
#pragma unroll
    for (int l = 0; l < 2; l++)
        aReg[l] = *(const float4*)&A[(size_t)(bm + rowA + l * 32) * DIM + kqA];
#pragma unroll
    for (int l = 0; l < 4; l++)
        bReg[l] = *(const float4*)&W[(size_t)(rB + l * 4) * DIM + wcol + cB];

    float acc[8][8];
#pragma unroll
    for (int i = 0; i < 8; i++)
#pragma unroll
        for (int j = 0; j < 8; j++) acc[i][j] = 0.f;

    for (int k0 = 0; k0 < DIM; k0 += 16) {
#pragma unroll
        for (int l = 0; l < 2; l++) {
            As[kqA + 0][rowA + l * 32] = aReg[l].x;
            As[kqA + 1][rowA + l * 32] = aReg[l].y;
            As[kqA + 2][rowA + l * 32] = aReg[l].z;
            As[kqA + 3][rowA + l * 32] = aReg[l].w;
        }
#pragma unroll
        for (int l = 0; l < 4; l++)
            *(float4*)&Bs[rB + l * 4][cB] = bReg[l];
        __syncthreads();
        if (k0 + 16 < DIM) {
#pragma unroll
            for (int l = 0; l < 2; l++)
                aReg[l] = *(const float4*)&A[(size_t)(bm + rowA + l * 32) * DIM + k0 + 16 + kqA];
#pragma unroll
            for (int l = 0; l < 4; l++)
                bReg[l] = *(const float4*)&W[(size_t)(k0 + 16 + rB + l * 4) * DIM + wcol + cB];
        }
#pragma unroll
        for (int kk = 0; kk < 16; kk++) {
            float4 a0 = *(const float4*)&As[kk][ty * 4];
            float4 a1 = *(const float4*)&As[kk][32 + ty * 4];
            float4 b0 = *(const float4*)&Bs[kk][tx * 4];
            float4 b1 = *(const float4*)&Bs[kk][64 + tx * 4];
            float av[8] = {a0.x, a0.y, a0.z, a0.w, a1.x, a1.y, a1.z, a1.w};
            float bv[8] = {b0.x, b0.y, b0.z, b0.w, b1.x, b1.y, b1.z, b1.w};
#pragma unroll
            for (int i = 0; i < 8; i++)
#pragma unroll
                for (int j = 0; j < 8; j++) acc[i][j] += av[i] * bv[j];
        }
        __syncthreads();
    }

    float4 bi0 = *(const float4*)&bias[wcol + tx * 4];
    float4 bi1 = *(const float4*)&bias[wcol + 64 + tx * 4];
    float bb0[4] = {bi0.x, bi0.y, bi0.z, bi0.w};
    float bb1[4] = {bi1.x, bi1.y, bi1.z, bi1.w};
#pragma unroll
    for (int i = 0; i < 8; i++) {
        int rowg = bm + (i >> 2) * 32 + ty * 4 + (i & 3);
        float v[8];
#pragma unroll
        for (int j = 0; j < 4; j++) {
            float u0 = acc[i][j] + bb0[j];
            float u1 = acc[i][4 + j] + bb1[j];
            if (gelu) {
                u0 = 0.5f * u0 * (1.f + erff(u0 * 0.70710678118654752f));
                u1 = 0.5f * u1 * (1.f + erff(u1 * 0.70710678118654752f));
            }
            v[j] = u0; v[4 + j] = u1;
        }
        float4 o0 = {v[0], v[1], v[2], v[3]};
        float4 o1 = {v[4], v[5], v[6], v[7]};
        *(float4*)&C[(size_t)rowg * DIM + wcol + tx * 4] = o0;
        *(float4*)&C[(size_t)rowg * DIM + wcol + 64 + tx * 4] = o1;
    }
}

// QKV: grid (9, 32); col blocks 0-2 -> Q, 3-5 -> K, 6-8 -> V
__global__ __launch_bounds__(128) void qkv_k(
    const float* __restrict__ qw, const float* __restrict__ qb,
    const float* __restrict__ kw, const float* __restrict__ kb,
    const float* __restrict__ vw, const float* __restrict__ vb) {
    int nb = blockIdx.x;
    const float* W; const float* bias; float* out;
    if (nb < 3)      { W = qw; bias = qb; out = g_q; }
    else if (nb < 6) { W = kw; bias = kb; out = g_kk; nb -= 3; }
    else             { W = vw; bias = vb; out = g_v;  nb -= 6; }
    gemm64x128(g_clusters, W, bias, out, blockIdx.y * 64, nb * 128, 0);
}

// MLP chain: mode 0: g_mid@nw->g_t1; 1: g_t1@m1w(+gelu)->g_t2; 2: g_t2@m2w->g_c2
__global__ __launch_bounds__(128) void mlp_k(const float* __restrict__ W,
                                             const float* __restrict__ bias,
                                             int mode) {
    const float* A = (mode == 0) ? g_mid : (mode == 1) ? g_t1 : g_t2;
    float* C = (mode == 0) ? g_t1 : (mode == 1) ? g_t2 : g_c2;
    gemm64x128(A, W, bias, C, blockIdx.y * 64, blockIdx.x * 128, (mode == 1) ? 1 : 0);
}

// ---------------- attention middle: scores/softmax/AV/hypergraph/L@AV -------------
__global__ __launch_bounds__(384) void attn_mid_k(const float* __restrict__ ew,
                                                  const float* __restrict__ eb) {
    extern __shared__ float sm[];
    float* Qs = sm;            // 16x384 (reused as AV)
    float* Ks = sm + 6144;
    float* Vs = sm + 12288;
    __shared__ float sc[256];
    __shared__ float hsc[KC * EE];
    __shared__ float rDd[EE];
    __shared__ float Lm[EE * EE];
    int b = blockIdx.x, t = threadIdx.x;
    size_t base = (size_t)b * KC * DIM;

#pragma unroll
    for (int k = 0; k < KC; k++) {
        Qs[k * DIM + t] = g_q[base + k * DIM + t];
        Ks[k * DIM + t] = g_kk[base + k * DIM + t];
        Vs[k * DIM + t] = g_v[base + k * DIM + t];
    }
    __syncthreads();
    if (t < 256) {
        int q = t >> 4, kk = t & 15;
        const float4* Q4 = (const float4*)Qs;
        const float4* K4 = (const float4*)Ks;
        float s = 0.f;
        for (int i = 0; i < 96; i++) {
            float4 a = Q4[q * 96 + i];
            float4 c = K4[kk * 96 + i];
            s += a.x * c.x + a.y * c.y + a.z * c.z + a.w * c.w;
        }
        sc[t] = s * 0.05103103630798288f;
    }
    __syncthreads();
    if (t < KC) {
        float m = -1e30f;
#pragma unroll
        for (int k = 0; k < KC; k++) m = fmaxf(m, sc[t * 16 + k]);
        float e[KC], su = 0.f;
#pragma unroll
        for (int k = 0; k < KC; k++) { e[k] = expf(sc[t * 16 + k] - m); su += e[k]; }
        float inv = 1.f / su;
#pragma unroll
        for (int k = 0; k < KC; k++) sc[t * 16 + k] = e[k] * inv;
    }
    __syncthreads();
    {
        float nv[KC];
#pragma unroll
        for (int q = 0; q < KC; q++) {
            float s = 0.f;
#pragma unroll
            for (int k = 0; k < KC; k++) s += sc[q * 16 + k] * Vs[k * DIM + t];
            nv[q] = s;
        }
        __syncthreads();
#pragma unroll
        for (int q = 0; q < KC; q++) Qs[q * DIM + t] = nv[q];   // AV
    }
    __syncthreads();
    if (t < 128) {
        int k = t >> 3, e = t & 7;
        float s = 0.f;
        for (int d = 0; d < DIM; d++) s += Qs[k * DIM + d] * ew[d * EE + e];
        hsc[k * EE + e] = s + eb[e];
    }
    __syncthreads();
    if (t < EE) {
        float m = -1e30f;
#pragma unroll
        for (int k = 0; k < KC; k++) m = fmaxf(m, hsc[k * EE + t]);
        float ex[KC], su = 0.f;
#pragma unroll
        for (int k = 0; k < KC; k++) { ex[k] = expf(hsc[k * EE + t] - m); su += ex[k]; }
        float inv = 1.f / su, dd = 0.f;
#pragma unroll
        for (int k = 0; k < KC; k++) { float h = ex[k] * inv; hsc[k * EE + t] = h; dd += h; }
        rDd[t] = 1.f / sqrtf(dd);
    }
    __syncthreads();
    if (t < 64) {
        int e = t >> 3, f = t & 7;
        float s = 0.f;
#pragma unroll
        for (int k = 0; k < KC; k++) s += hsc[k * EE + e] * hsc[k * EE + f];
        Lm[t] = ((e == f) ? 1.f : 0.f) - rDd[e] * s;
    }
    __syncthreads();
    {
        float lv[EE];
#pragma unroll
        for (int i = 0; i < EE; i++) {
            float s = 0.f;
#pragma unroll
            for (int f = 0; f < EE; f++) s += Lm[i * EE + f] * Qs[f * DIM + t];
            lv[i] = s;
        }
#pragma unroll
        for (int i = 0; i < EE; i++) g_mid[base + i * DIM + t] = lv[i];
#pragma unroll
        for (int i = EE; i < KC; i++) g_mid[base + i * DIM + t] = 0.f;
    }
}

// ---------------- cosine-similarity mask over batch ----------------
__global__ __launch_bounds__(384) void mask_k() {
    __shared__ float A[KC * DIM];
    __shared__ float pna[256];
    __shared__ float nrm[KC];
    int b = blockIdx.x, t = threadIdx.x;
    size_t base = (size_t)b * KC * DIM;
#pragma unroll
    for (int k = 0; k < KC; k++) A[k * DIM + t] = g_c2[base + k * DIM + t];
    __syncthreads();
    if (t < 256) {
        int k = t >> 4, l = t & 15;
        float s = 0.f;
#pragma unroll
        for (int i = 0; i < 24; i++) {
            float v = A[k * DIM + l + 16 * i];
            s += v * v;
        }
        pna[t] = s;
    }
    __syncthreads();
    if (t < KC) {
        float s = 0.f;
#pragma unroll
        for (int l = 0; l < 16; l++) s += pna[t * 16 + l];
        nrm[t] = fmaxf(sqrtf(s), 1e-12f);
    }
    __syncthreads();
    if (t < 120) {
        int i = 0, rem = t, cnt = 15;
        while (rem >= cnt) { rem -= cnt; cnt--; i++; }
        int j = i + 1 + rem;
        float s = 0.f;
        for (int d = 0; d < DIM; d++) s += A[i * DIM + d] * A[j * DIM + d];
        if (s / (nrm[i] * nrm[j]) > 0.9f) atomicOr(&g_mask[i * 16 + j], 1u);
    }
}

// ---------------- sequential merge + gated fusion (block = batch) ----------------
__global__ __launch_bounds__(384) void merge_k(const float* __restrict__ fbw,
                                               const float* __restrict__ fbb,
                                               const float* __restrict__ fgw,
                                               const float* __restrict__ fgb) {
    __shared__ unsigned int msk[256];
    __shared__ float gsh[DIM];
    __shared__ float wsum[12];
    __shared__ float gate_s;
    int b = blockIdx.x, t = threadIdx.x;
    if (t < 256) msk[t] = g_mask[t];
    float c[KC];
#pragma unroll
    for (int k = 0; k < KC; k++) c[k] = g_c2[(size_t)b * KC * DIM + k * DIM + t];
    __syncthreads();
#pragma unroll
    for (int i = 0; i < KC; i++)
#pragma unroll
        for (int j = i + 1; j < KC; j++)
            if (msk[i * 16 + j]) {
                float m = (c[i] + c[j]) * 0.5f;
                c[i] = m;
                c[j] = m;
            }
    float g = 0.f;
#pragma unroll
    for (int k = 0; k < KC; k++) g += c[k];
    g *= (1.f / 16.f);
    gsh[t] = g;
    float p = g * fgw[t];
#pragma unroll
    for (int o = 16; o > 0; o >>= 1) p += __shfl_xor_sync(0xffffffffu, p, o);
    if ((t & 31) == 0) wsum[t >> 5] = p;
    __syncthreads();
    if (t == 0) {
        float s = 0.f;
#pragma unroll
        for (int i = 0; i < 12; i++) s += wsum[i];
        gate_s = 1.f / (1.f + expf(-(s + fgb[0])));
    }
    __syncthreads();
    float gate = gate_s;
    float acc = 0.f;
    for (int d = 0; d < DIM; d++) acc += gsh[d] * fbw[d * DIM + t];
    float fb = acc + fbb[t];
#pragma unroll
    for (int k = 0; k < KC; k++)
        g_flat[(size_t)b * KC * DIM + k * DIM + t] = c[k] + fb * gate;
}

// ---------------- classifier: [128,6144] @ [6144,1000], split-K ----------------
__global__ __launch_bounds__(256) void cls_k(const float* __restrict__ cw) {
    __shared__ float As[16][132];
    __shared__ float Bs[16][68];
    int bn = blockIdx.x * 64;
    int kz = blockIdx.z;
    int kbase = kz * (KC * DIM / KSPLIT);
    int tid = threadIdx.x;
    int ty = tid >> 4, tx = tid & 15;
    float acc[8][4];
#pragma unroll
    for (int i = 0; i < 8; i++)
#pragma unroll
        for (int j = 0; j < 4; j++) acc[i][j] = 0.f;

    for (int k0 = kbase; k0 < kbase + 768; k0 += 16) {
#pragma unroll
        for (int l = 0; l < 2; l++) {
            int s = tid + l * 256;
            int row = s >> 2, kq = s & 3;
            float4 av = *(const float4*)&g_flat[(size_t)row * (KC * DIM) + k0 + kq * 4];
            As[kq * 4 + 0][row] = av.x;
            As[kq * 4 + 1][row] = av.y;
            As[kq * 4 + 2][row] = av.z;
            As[kq * 4 + 3][row] = av.w;
        }
#pragma unroll
        for (int j = 0; j < 4; j++) {
            int idx = tid * 4 + j;
            int row = idx >> 6, cc = idx & 63;
            int n = bn + cc;
            Bs[row][cc] = (n < NCLS) ? cw[(size_t)(k0 + row) * NCLS + n] : 0.f;
        }
        __syncthreads();
#pragma unroll
        for (int kk = 0; kk < 16; kk++) {
            float4 a0 = *(const float4*)&As[kk][ty * 8];
            float4 a1 = *(const float4*)&As[kk][ty * 8 + 4];
            float4 bb = *(const float4*)&Bs[kk][tx * 4];
            float av[8] = {a0.x, a0.y, a0.z, a0.w, a1.x, a1.y, a1.z, a1.w};
            float bv[4] = {bb.x, bb.y, bb.z, bb.w};
#pragma unroll
            for (int i = 0; i < 8; i++)
#pragma unroll
                for (int j = 0; j < 4; j++) acc[i][j] += av[i] * bv[j];
        }
        __syncthreads();
    }
    float* part = g_cpart + (size_t)kz * BATCH * NCLS;
#pragma unroll
    for (int i = 0; i < 8; i++)
#pragma unroll
        for (int j = 0; j < 4; j++) {
            int n = bn + tx * 4 + j;
            if (n < NCLS) part[(ty * 8 + i) * NCLS + n] = acc[i][j];
        }
}

__global__ void finout_k(const float* __restrict__ cb, float* __restrict__ out) {
    int idx = blockIdx.x * 256 + threadIdx.x;
    if (idx >= BATCH * NCLS) return;
    int n = idx % NCLS;
    float s = cb[n];
#pragma unroll
    for (int z = 0; z < KSPLIT; z++) s += g_cpart[(size_t)z * BATCH * NCLS + idx];
    out[idx] = s;
}

extern "C" void kernel_launch(void* const* d_in, const int* in_sizes, int n_in,
                              void* d_out, int out_size) {
    const float* x    = (const float*)d_in[0];
    const float* pw   = (const float*)d_in[1];
    const float* pb   = (const float*)d_in[2];
    const float* ln_g = (const float*)d_in[3];
    const float* ln_b = (const float*)d_in[4];
    const float* pos  = (const float*)d_in[5];
    const float* qw   = (const float*)d_in[6];
    const float* qb   = (const float*)d_in[7];
    const float* kw   = (const float*)d_in[8];
    const float* kb   = (const float*)d_in[9];
    const float* vw   = (const float*)d_in[10];
    const float* vb   = (const float*)d_in[11];
    const float* ew   = (const float*)d_in[12];
    const float* eb   = (const float*)d_in[13];
    const float* nw   = (const float*)d_in[14];
    const float* nb   = (const float*)d_in[15];
    const float* m1w  = (const float*)d_in[16];
    const float* m1b  = (const float*)d_in[17];
    const float* m2w  = (const float*)d_in[18];
    const float* m2b  = (const float*)d_in[19];
    const float* fbw  = (const float*)d_in[20];
    const float* fbb  = (const float*)d_in[21];
    const float* fgw  = (const float*)d_in[22];
    const float* fgb  = (const float*)d_in[23];
    const float* cw   = (const float*)d_in[24];
    const float* cb   = (const float*)d_in[25];
    float* out = (float*)d_out;

    cudaFuncSetAttribute(kmeans_k,   cudaFuncAttributeMaxDynamicSharedMemorySize, 49152);
    cudaFuncSetAttribute(attn_mid_k, cudaFuncAttributeMaxDynamicSharedMemorySize, 73728);

    gemm_patch<<<dim3(3, 98), 256>>>(x, pw, pb);
    ln_k<<<BATCH * NPTS, 128>>>(ln_g, ln_b);
    kmeans_k<<<BATCH, 512, 49152>>>(pos);
    qkv_k<<<dim3(9, 32), 128>>>(qw, qb, kw, kb, vw, vb);
    attn_mid_k<<<BATCH, 384, 73728>>>(ew, eb);
    mlp_k<<<dim3(3, 32), 128>>>(nw, nb, 0);
    mlp_k<<<dim3(3, 32), 128>>>(m1w, m1b, 1);
    mlp_k<<<dim3(3, 32), 128>>>(m2w, m2b, 2);
    mask_k<<<BATCH, 384>>>();
    merge_k<<<BATCH, 384>>>(fbw, fbb, fgw, fgb);
    cls_k<<<dim3(16, 1, KSPLIT), 256>>>(cw);
    finout_k<<<(BATCH * NCLS + 255) / 256, 256>>>(cb, out);
}